// round 1
// baseline (speedup 1.0000x reference)
#include <cuda_runtime.h>

// ---------------- problem constants (fixed by setup_inputs) ----------------
#define B_SZ   2
#define N_TOK  32768
#define DIM    512
#define HEADS  8
#define DH     64
#define NGRAPH 32
#define QKV3   1536                    // 3 * HEADS * DH
#define M_ROWS (B_SZ * N_TOK)          // 65536

// ---------------- device scratch (static: no allocations allowed) ----------
__device__ float g_qkv [(size_t)M_ROWS * QKV3];        // 402 MB
__device__ float g_attn[(size_t)M_ROWS * DIM];         // 134 MB
__device__ float g_ktv [B_SZ * HEADS * NGRAPH * DH * DH];
__device__ float g_wqkvT[DIM * QKV3];
__device__ float g_woutT[DIM * DIM];
__device__ int   g_sizes[NGRAPH];
__device__ int   g_off  [NGRAPH + 1];

// ---------------- segment histogram / offsets ------------------------------
__global__ void hist_kernel(const int* __restrict__ batch) {
    __shared__ int cnt[NGRAPH];
    int tid = threadIdx.x;
    if (tid < NGRAPH) cnt[tid] = 0;
    __syncthreads();
    for (int i = tid; i < N_TOK; i += 256) atomicAdd(&cnt[batch[i]], 1);
    __syncthreads();
    if (tid == 0) {
        int off = 0;
        for (int g = 0; g < NGRAPH; g++) {
            g_off[g] = off; g_sizes[g] = cnt[g]; off += cnt[g];
        }
        g_off[NGRAPH] = off;
    }
}

// ---------------- tiled transpose (rows, cols both /32) --------------------
__global__ void transpose_kernel(const float* __restrict__ src,
                                 float* __restrict__ dst, int rows, int cols) {
    __shared__ float tile[32][33];
    int x = blockIdx.x * 32 + threadIdx.x;      // col in src
    int y = blockIdx.y * 32 + threadIdx.y;      // row in src
#pragma unroll
    for (int j = 0; j < 32; j += 8)
        tile[threadIdx.y + j][threadIdx.x] = src[(size_t)(y + j) * cols + x];
    __syncthreads();
    x = blockIdx.y * 32 + threadIdx.x;          // col in dst (= src row)
    y = blockIdx.x * 32 + threadIdx.y;          // row in dst (= src col)
#pragma unroll
    for (int j = 0; j < 32; j += 8)
        dst[(size_t)(y + j) * rows + x] = tile[threadIdx.x][threadIdx.y + j];
}

// ---------------- SGEMM: C[M,Nc] = A[M,K] @ B[K,Nc] (+bias) ----------------
// BM=BN=128, BK=8, 256 threads, 8x8 per thread. M%128==0, Nc%128==0, K%8==0.
template <bool BIAS>
__global__ __launch_bounds__(256)
void sgemm_kernel(const float* __restrict__ A, const float* __restrict__ Bm,
                  float* __restrict__ C, const float* __restrict__ bias,
                  int M, int Nc, int K) {
    __shared__ __align__(16) float As[8][128];
    __shared__ __align__(16) float Bs[8][128];

    int tid = threadIdx.x;
    const float* Ab = A + (size_t)blockIdx.y * 128 * K;
    const float* Bb = Bm + blockIdx.x * 128;

    int arow  = tid >> 1;             // 0..127
    int acol  = (tid & 1) * 4;        // 0 or 4
    int brow  = tid >> 5;             // 0..7
    int bcol  = (tid & 31) * 4;       // 0..124
    int ty    = tid >> 4;             // 0..15
    int tx    = tid & 15;             // 0..15

    float acc[8][8];
#pragma unroll
    for (int i = 0; i < 8; i++)
#pragma unroll
        for (int j = 0; j < 8; j++) acc[i][j] = 0.0f;

    for (int k0 = 0; k0 < K; k0 += 8) {
        float4 av = *(const float4*)(Ab + (size_t)arow * K + k0 + acol);
        As[acol + 0][arow] = av.x; As[acol + 1][arow] = av.y;
        As[acol + 2][arow] = av.z; As[acol + 3][arow] = av.w;
        *(float4*)&Bs[brow][bcol] =
            *(const float4*)(Bb + (size_t)(k0 + brow) * Nc + bcol);
        __syncthreads();
#pragma unroll
        for (int kk = 0; kk < 8; kk++) {
            float ra[8], rb[8];
            *(float4*)&ra[0] = *(float4*)&As[kk][ty * 8];
            *(float4*)&ra[4] = *(float4*)&As[kk][ty * 8 + 4];
            *(float4*)&rb[0] = *(float4*)&Bs[kk][tx * 8];
            *(float4*)&rb[4] = *(float4*)&Bs[kk][tx * 8 + 4];
#pragma unroll
            for (int i = 0; i < 8; i++)
#pragma unroll
                for (int j = 0; j < 8; j++)
                    acc[i][j] += ra[i] * rb[j];
        }
        __syncthreads();
    }

    int ccol = blockIdx.x * 128 + tx * 8;
#pragma unroll
    for (int i = 0; i < 8; i++) {
        size_t crow = (size_t)blockIdx.y * 128 + ty * 8 + i;
        float* cp = C + crow * Nc + ccol;
        float4 w0 = make_float4(acc[i][0], acc[i][1], acc[i][2], acc[i][3]);
        float4 w1 = make_float4(acc[i][4], acc[i][5], acc[i][6], acc[i][7]);
        if (BIAS) {
            float4 b0 = *(const float4*)(bias + ccol);
            float4 b1 = *(const float4*)(bias + ccol + 4);
            w0.x += b0.x; w0.y += b0.y; w0.z += b0.z; w0.w += b0.w;
            w1.x += b1.x; w1.y += b1.y; w1.z += b1.z; w1.w += b1.w;
        }
        *(float4*)cp       = w0;
        *(float4*)(cp + 4) = w1;
    }
}

// ---------------- LN(k), LN(v), q /= size[batch[n]] (in place) -------------
// one warp per (b*N+n, h); 8 warps/block
__global__ __launch_bounds__(256)
void ln_scale_kernel(const int* __restrict__ batch,
                     const float* __restrict__ ln1w, const float* __restrict__ ln1b,
                     const float* __restrict__ ln2w, const float* __restrict__ ln2b) {
    int warp = threadIdx.x >> 5, lane = threadIdx.x & 31;
    size_t task = (size_t)blockIdx.x * 8 + warp;
    int h = (int)(task & 7);
    size_t bn = task >> 3;                       // 0..M_ROWS-1
    int n = (int)(bn & (N_TOK - 1));
    float* base = g_qkv + bn * QKV3 + h * DH;

    float inv = 1.0f / (float)g_sizes[batch[n]];
    base[lane]      *= inv;
    base[lane + 32] *= inv;

#pragma unroll
    for (int part = 0; part < 2; part++) {
        float* p = base + 512 + part * 512;      // k then v
        const float* w = part ? ln2w : ln1w;
        const float* bb = part ? ln2b : ln1b;
        float a = p[lane], c = p[lane + 32];
        float s = a + c;
#pragma unroll
        for (int o = 16; o; o >>= 1) s += __shfl_xor_sync(0xffffffffu, s, o);
        float mu = s * (1.0f / 64.0f);
        float d0 = a - mu, d1 = c - mu;
        float vv = d0 * d0 + d1 * d1;
#pragma unroll
        for (int o = 16; o; o >>= 1) vv += __shfl_xor_sync(0xffffffffu, vv, o);
        float rs = rsqrtf(vv * (1.0f / 64.0f) + 1e-6f);
        p[lane]      = d0 * rs * w[lane]      + bb[lane];
        p[lane + 32] = d1 * rs * w[lane + 32] + bb[lane + 32];
    }
}

// ---------------- ktv[b,h,g] = K_segT @ V_seg  (64x64) ---------------------
// one block per (b,h,g): blockIdx.x = ((b*H+h)*G+g)
__global__ __launch_bounds__(256)
void ktv_kernel() {
    int g = blockIdx.x & 31;
    int h = (blockIdx.x >> 5) & 7;
    int b = blockIdx.x >> 8;
    int s0 = g_off[g], s1 = g_off[g + 1];

    __shared__ __align__(16) float sk[32][64];
    __shared__ __align__(16) float sv[32][64];

    int tid = threadIdx.x;
    int ti = tid >> 3;             // token within chunk (0..31)
    int jb = (tid & 7) * 8;        // 8 floats per thread
    int i0 = (tid >> 4) * 4;
    int j0 = (tid & 15) * 4;

    float acc[4][4];
#pragma unroll
    for (int i = 0; i < 4; i++)
#pragma unroll
        for (int j = 0; j < 4; j++) acc[i][j] = 0.0f;

    for (int t0 = s0; t0 < s1; t0 += 32) {
        int n = t0 + ti;
        if (n < s1) {
            const float* row = g_qkv + ((size_t)b * N_TOK + n) * QKV3 + 512 + h * DH + jb;
            *(float4*)&sk[ti][jb]     = *(const float4*)(row);
            *(float4*)&sk[ti][jb + 4] = *(const float4*)(row + 4);
            *(float4*)&sv[ti][jb]     = *(const float4*)(row + 512);
            *(float4*)&sv[ti][jb + 4] = *(const float4*)(row + 516);
        } else {
            float4 z = make_float4(0.f, 0.f, 0.f, 0.f);
            *(float4*)&sk[ti][jb] = z; *(float4*)&sk[ti][jb + 4] = z;
            *(float4*)&sv[ti][jb] = z; *(float4*)&sv[ti][jb + 4] = z;
        }
        __syncthreads();
#pragma unroll
        for (int t = 0; t < 32; t++) {
            float4 ka = *(float4*)&sk[t][i0];
            float4 vb = *(float4*)&sv[t][j0];
            acc[0][0] += ka.x * vb.x; acc[0][1] += ka.x * vb.y;
            acc[0][2] += ka.x * vb.z; acc[0][3] += ka.x * vb.w;
            acc[1][0] += ka.y * vb.x; acc[1][1] += ka.y * vb.y;
            acc[1][2] += ka.y * vb.z; acc[1][3] += ka.y * vb.w;
            acc[2][0] += ka.z * vb.x; acc[2][1] += ka.z * vb.y;
            acc[2][2] += ka.z * vb.z; acc[2][3] += ka.z * vb.w;
            acc[3][0] += ka.w * vb.x; acc[3][1] += ka.w * vb.y;
            acc[3][2] += ka.w * vb.z; acc[3][3] += ka.w * vb.w;
        }
        __syncthreads();
    }

    float* out = g_ktv + (size_t)blockIdx.x * DH * DH;
#pragma unroll
    for (int i = 0; i < 4; i++)
        *(float4*)&out[(i0 + i) * DH + j0] =
            make_float4(acc[i][0], acc[i][1], acc[i][2], acc[i][3]);
}

// ---------------- attn[n] = qn[n] @ ktv[batch[n]] ---------------------------
// one block per (b,h,g); tiles of 64 tokens
__global__ __launch_bounds__(256)
void apply_kernel() {
    int g = blockIdx.x & 31;
    int h = (blockIdx.x >> 5) & 7;
    int b = blockIdx.x >> 8;
    int s0 = g_off[g], s1 = g_off[g + 1];

    __shared__ __align__(16) float kt[DH * DH];
    __shared__ __align__(16) float sq[64][68];

    int tid = threadIdx.x;
    const float* ktg = g_ktv + (size_t)blockIdx.x * DH * DH;
#pragma unroll
    for (int i = 0; i < 16; i++) kt[i * 256 + tid] = ktg[i * 256 + tid];

    int t_ld = tid >> 2;            // 0..63
    int j_ld = (tid & 3) * 16;      // 0,16,32,48
    int t0q  = (tid >> 4) * 4;      // 4 tokens per thread
    int j0   = (tid & 15) * 4;      // 4 cols per thread

    for (int base = s0; base < s1; base += 64) {
        int n = base + t_ld;
        if (n < s1) {
            const float* qrow = g_qkv + ((size_t)b * N_TOK + n) * QKV3 + h * DH;
#pragma unroll
            for (int c = 0; c < 4; c++)
                *(float4*)&sq[t_ld][j_ld + c * 4] = *(const float4*)(qrow + j_ld + c * 4);
        } else {
            float4 z = make_float4(0.f, 0.f, 0.f, 0.f);
#pragma unroll
            for (int c = 0; c < 4; c++) *(float4*)&sq[t_ld][j_ld + c * 4] = z;
        }
        __syncthreads();

        float acc[4][4];
#pragma unroll
        for (int i = 0; i < 4; i++)
#pragma unroll
            for (int j = 0; j < 4; j++) acc[i][j] = 0.0f;

#pragma unroll
        for (int i = 0; i < DH; i++) {
            float4 kv = *(float4*)&kt[i * DH + j0];
            float q0 = sq[t0q + 0][i], q1 = sq[t0q + 1][i];
            float q2 = sq[t0q + 2][i], q3 = sq[t0q + 3][i];
            acc[0][0] += q0 * kv.x; acc[0][1] += q0 * kv.y;
            acc[0][2] += q0 * kv.z; acc[0][3] += q0 * kv.w;
            acc[1][0] += q1 * kv.x; acc[1][1] += q1 * kv.y;
            acc[1][2] += q1 * kv.z; acc[1][3] += q1 * kv.w;
            acc[2][0] += q2 * kv.x; acc[2][1] += q2 * kv.y;
            acc[2][2] += q2 * kv.z; acc[2][3] += q2 * kv.w;
            acc[3][0] += q3 * kv.x; acc[3][1] += q3 * kv.y;
            acc[3][2] += q3 * kv.z; acc[3][3] += q3 * kv.w;
        }
        __syncthreads();

#pragma unroll
        for (int tt = 0; tt < 4; tt++) {
            int n2 = base + t0q + tt;
            if (n2 < s1) {
                float* orow = g_attn + ((size_t)b * N_TOK + n2) * DIM + h * DH + j0;
                *(float4*)orow = make_float4(acc[tt][0], acc[tt][1], acc[tt][2], acc[tt][3]);
            }
        }
    }
}

// ---------------- launch ----------------------------------------------------
extern "C" void kernel_launch(void* const* d_in, const int* in_sizes, int n_in,
                              void* d_out, int out_size) {
    const float* x      = (const float*)d_in[0];
    const float* w_qkv  = (const float*)d_in[1];
    const float* ln1w   = (const float*)d_in[2];
    const float* ln1b   = (const float*)d_in[3];
    const float* ln2w   = (const float*)d_in[4];
    const float* ln2b   = (const float*)d_in[5];
    const float* w_out  = (const float*)d_in[6];
    const float* b_out  = (const float*)d_in[7];
    const int*   batch  = (const int*)d_in[8];
    float* out = (float*)d_out;

    float *qkv_p, *attn_p, *wqkvT_p, *woutT_p;
    cudaGetSymbolAddress((void**)&qkv_p,   g_qkv);
    cudaGetSymbolAddress((void**)&attn_p,  g_attn);
    cudaGetSymbolAddress((void**)&wqkvT_p, g_wqkvT);
    cudaGetSymbolAddress((void**)&woutT_p, g_woutT);

    // 0) segment offsets + sizes
    hist_kernel<<<1, 256>>>(batch);

    // 1) transpose weights to [K, Nc]
    transpose_kernel<<<dim3(DIM / 32, QKV3 / 32), dim3(32, 8)>>>(w_qkv, wqkvT_p, QKV3, DIM);
    transpose_kernel<<<dim3(DIM / 32, DIM / 32),  dim3(32, 8)>>>(w_out, woutT_p, DIM, DIM);

    // 2) qkv = x @ w_qkvT
    sgemm_kernel<false><<<dim3(QKV3 / 128, M_ROWS / 128), 256>>>(
        x, wqkvT_p, qkv_p, nullptr, M_ROWS, QKV3, DIM);

    // 3) LN(k), LN(v), q scaling — in place
    ln_scale_kernel<<<(M_ROWS * HEADS) / 8, 256>>>(batch, ln1w, ln1b, ln2w, ln2b);

    // 4) per-(b,h,g) ktv = K_segT @ V_seg
    ktv_kernel<<<B_SZ * HEADS * NGRAPH, 256>>>();

    // 5) attn = qn @ ktv[seg]
    apply_kernel<<<B_SZ * HEADS * NGRAPH, 256>>>();

    // 6) out = attn @ w_outT + b_out
    sgemm_kernel<true><<<dim3(DIM / 128, M_ROWS / 128), 256>>>(
        attn_p, woutT_p, out, b_out, M_ROWS, DIM, DIM);
}

// round 3
// speedup vs baseline: 2.1800x; 2.1800x over previous
#include <cuda_runtime.h>
#include <cuda_bf16.h>
#include <cstdint>

// ---------------- problem constants (fixed by setup_inputs) ----------------
#define B_SZ   2
#define N_TOK  32768
#define DIM    512
#define HEADS  8
#define DH     64
#define NGRAPH 32
#define QKV3   1536
#define M_ROWS (B_SZ * N_TOK)          // 65536
#define KDIM   512

// ---------------- device scratch (static; no allocations allowed) ----------
__device__ float         g_qkv [(size_t)M_ROWS * QKV3];
__device__ __nv_bfloat16 g_a_hi[(size_t)M_ROWS * KDIM];
__device__ __nv_bfloat16 g_a_lo[(size_t)M_ROWS * KDIM];
__device__ __nv_bfloat16 g_b1_hi[QKV3 * KDIM];
__device__ __nv_bfloat16 g_b1_lo[QKV3 * KDIM];
__device__ __nv_bfloat16 g_b2_hi[DIM * KDIM];
__device__ __nv_bfloat16 g_b2_lo[DIM * KDIM];
__device__ __nv_bfloat16 g_attn_hi[(size_t)M_ROWS * DIM];
__device__ __nv_bfloat16 g_attn_lo[(size_t)M_ROWS * DIM];
__device__ float g_ktv[B_SZ * HEADS * NGRAPH * DH * DH];
__device__ int   g_sizes[NGRAPH];
__device__ int   g_off  [NGRAPH + 1];

// ---------------- helpers ---------------------------------------------------
__device__ __forceinline__ uint32_t smem_u32(const void* p) {
    uint32_t a;
    asm("{ .reg .u64 t; cvta.to.shared.u64 t, %1; cvt.u32.u64 %0, t; }"
        : "=r"(a) : "l"(p));
    return a;
}
__device__ __forceinline__ uint32_t lds32(uint32_t a) {
    uint32_t v;
    asm("ld.shared.b32 %0, [%1];" : "=r"(v) : "r"(a));
    return v;
}
__device__ __forceinline__ void mma16816(float* d, const uint32_t* a, const uint32_t* b) {
    asm volatile(
        "mma.sync.aligned.m16n8k16.row.col.f32.bf16.bf16.f32 "
        "{%0,%1,%2,%3}, {%4,%5,%6,%7}, {%8,%9}, {%0,%1,%2,%3};"
        : "+f"(d[0]), "+f"(d[1]), "+f"(d[2]), "+f"(d[3])
        : "r"(a[0]), "r"(a[1]), "r"(a[2]), "r"(a[3]), "r"(b[0]), "r"(b[1]));
}

// ---------------- small kernels ---------------------------------------------
__global__ void hist_kernel(const int* __restrict__ batch) {
    __shared__ int cnt[NGRAPH];
    int tid = threadIdx.x;
    if (tid < NGRAPH) cnt[tid] = 0;
    __syncthreads();
    for (int i = tid; i < N_TOK; i += 256) atomicAdd(&cnt[batch[i]], 1);
    __syncthreads();
    if (tid == 0) {
        int off = 0;
        for (int g = 0; g < NGRAPH; g++) {
            g_off[g] = off; g_sizes[g] = cnt[g]; off += cnt[g];
        }
        g_off[NGRAPH] = off;
    }
}

// fp32 -> (bf16 hi, bf16 lo) split, vectorized x4
__global__ void conv_split_kernel(const float* __restrict__ src,
                                  __nv_bfloat16* __restrict__ hi,
                                  __nv_bfloat16* __restrict__ lo, long n4) {
    long i = (long)blockIdx.x * blockDim.x + threadIdx.x;
    long stride = (long)gridDim.x * blockDim.x;
    for (; i < n4; i += stride) {
        float4 v = ((const float4*)src)[i];
        __nv_bfloat16 h0 = __float2bfloat16_rn(v.x);
        __nv_bfloat16 h1 = __float2bfloat16_rn(v.y);
        __nv_bfloat16 h2 = __float2bfloat16_rn(v.z);
        __nv_bfloat16 h3 = __float2bfloat16_rn(v.w);
        __nv_bfloat16 l0 = __float2bfloat16_rn(v.x - __bfloat162float(h0));
        __nv_bfloat16 l1 = __float2bfloat16_rn(v.y - __bfloat162float(h1));
        __nv_bfloat16 l2 = __float2bfloat16_rn(v.z - __bfloat162float(h2));
        __nv_bfloat16 l3 = __float2bfloat16_rn(v.w - __bfloat162float(h3));
        ushort4 vh, vl;
        vh.x = __bfloat16_as_ushort(h0); vh.y = __bfloat16_as_ushort(h1);
        vh.z = __bfloat16_as_ushort(h2); vh.w = __bfloat16_as_ushort(h3);
        vl.x = __bfloat16_as_ushort(l0); vl.y = __bfloat16_as_ushort(l1);
        vl.z = __bfloat16_as_ushort(l2); vl.w = __bfloat16_as_ushort(l3);
        ((ushort4*)hi)[i] = vh;
        ((ushort4*)lo)[i] = vl;
    }
}

// ---------------- mma.sync split-bf16 GEMM ----------------------------------
// C[M,Nc] = (Ah+Al)[M,512] @ (Bh+Bl)[Nc,512]^T (+bias).
// CTA tile 128x128, BK=64, 8 warps (warp tile 32x64), cp.async double buffer.
#define STRW 36                     // smem row stride in 32-bit words (72 bf16)
#define TEN_BYTES (128 * 144)       // one tensor slab: 128 rows x 144B
#define STG_BYTES (4 * TEN_BYTES)   // 4 tensors per stage
#define MG_SMEM   (2 * STG_BYTES)   // 147456 B

__device__ __forceinline__ void issue_slab(uint32_t sdst, const __nv_bfloat16* g,
                                           int k0, int tid) {
#pragma unroll
    for (int t = 0; t < 4; t++) {
        int id  = tid + t * 256;
        int row = id >> 3, col = id & 7;
        uint32_t s = sdst + row * 144 + col * 16;
        const void* gp = g + (size_t)row * KDIM + k0 + col * 8;
        asm volatile("cp.async.cg.shared.global [%0], [%1], 16;" :: "r"(s), "l"(gp));
    }
}

__device__ __forceinline__ void compute_slab(uint32_t sAh, uint32_t sAl,
                                             uint32_t sBh, uint32_t sBl,
                                             float acc[2][8][4],
                                             int warpM, int warpN, int lane) {
    int g  = lane >> 2;
    int c2 = lane & 3;
#pragma unroll
    for (int kk = 0; kk < 4; kk++) {
        int kw = kk * 8 + c2;                    // word offset in row
        uint32_t ah[2][4], al[2][4], bh[8][2], bl[8][2];
#pragma unroll
        for (int mt = 0; mt < 2; mt++) {
            uint32_t o0 = ((warpM + mt * 16 + g) * STRW + kw) * 4;
            uint32_t o1 = o0 + 8 * STRW * 4;
            ah[mt][0] = lds32(sAh + o0);      ah[mt][1] = lds32(sAh + o1);
            ah[mt][2] = lds32(sAh + o0 + 16); ah[mt][3] = lds32(sAh + o1 + 16);
            al[mt][0] = lds32(sAl + o0);      al[mt][1] = lds32(sAl + o1);
            al[mt][2] = lds32(sAl + o0 + 16); al[mt][3] = lds32(sAl + o1 + 16);
        }
#pragma unroll
        for (int nt = 0; nt < 8; nt++) {
            uint32_t o = ((warpN + nt * 8 + g) * STRW + kw) * 4;
            bh[nt][0] = lds32(sBh + o); bh[nt][1] = lds32(sBh + o + 16);
            bl[nt][0] = lds32(sBl + o); bl[nt][1] = lds32(sBl + o + 16);
        }
#pragma unroll
        for (int mt = 0; mt < 2; mt++)
#pragma unroll
            for (int nt = 0; nt < 8; nt++) {
                mma16816(acc[mt][nt], ah[mt], bh[nt]);
                mma16816(acc[mt][nt], ah[mt], bl[nt]);
                mma16816(acc[mt][nt], al[mt], bh[nt]);
            }
    }
}

template <bool BIAS>
__global__ __launch_bounds__(256)
void mgemm_kernel(const __nv_bfloat16* __restrict__ Ah, const __nv_bfloat16* __restrict__ Al,
                  const __nv_bfloat16* __restrict__ Bh, const __nv_bfloat16* __restrict__ Bl,
                  float* __restrict__ C, const float* __restrict__ bias, int Nc) {
    extern __shared__ __align__(16) char smem[];
    uint32_t sb = smem_u32(smem);
    int tid = threadIdx.x, wid = tid >> 5, lane = tid & 31;
    int warpM = (wid & 3) * 32;      // 4 warps along M
    int warpN = (wid >> 2) * 64;     // 2 warps along N

    const __nv_bfloat16* pAh = Ah + (size_t)blockIdx.y * 128 * KDIM;
    const __nv_bfloat16* pAl = Al + (size_t)blockIdx.y * 128 * KDIM;
    const __nv_bfloat16* pBh = Bh + (size_t)blockIdx.x * 128 * KDIM;
    const __nv_bfloat16* pBl = Bl + (size_t)blockIdx.x * 128 * KDIM;

#define ST(s, t) (sb + (s) * STG_BYTES + (t) * TEN_BYTES)

    issue_slab(ST(0, 0), pAh, 0, tid);
    issue_slab(ST(0, 1), pAl, 0, tid);
    issue_slab(ST(0, 2), pBh, 0, tid);
    issue_slab(ST(0, 3), pBl, 0, tid);
    asm volatile("cp.async.commit_group;");
    issue_slab(ST(1, 0), pAh, 64, tid);
    issue_slab(ST(1, 1), pAl, 64, tid);
    issue_slab(ST(1, 2), pBh, 64, tid);
    issue_slab(ST(1, 3), pBl, 64, tid);
    asm volatile("cp.async.commit_group;");

    float acc[2][8][4];
#pragma unroll
    for (int i = 0; i < 2; i++)
#pragma unroll
        for (int j = 0; j < 8; j++)
#pragma unroll
            for (int k = 0; k < 4; k++) acc[i][j][k] = 0.0f;

    for (int i = 0; i < 8; i++) {
        int s = i & 1;
        if (i < 7) asm volatile("cp.async.wait_group 1;");
        else       asm volatile("cp.async.wait_group 0;");
        __syncthreads();
        compute_slab(ST(s, 0), ST(s, 1), ST(s, 2), ST(s, 3), acc, warpM, warpN, lane);
        __syncthreads();
        if (i + 2 < 8) {
            int k0 = (i + 2) * 64;
            issue_slab(ST(s, 0), pAh, k0, tid);
            issue_slab(ST(s, 1), pAl, k0, tid);
            issue_slab(ST(s, 2), pBh, k0, tid);
            issue_slab(ST(s, 3), pBl, k0, tid);
            asm volatile("cp.async.commit_group;");
        }
    }

    // epilogue
    int g = lane >> 2, c2 = lane & 3;
#pragma unroll
    for (int mt = 0; mt < 2; mt++) {
        size_t m0 = (size_t)blockIdx.y * 128 + warpM + mt * 16 + g;
#pragma unroll
        for (int nt = 0; nt < 8; nt++) {
            int nc = blockIdx.x * 128 + warpN + nt * 8 + c2 * 2;
            float2 v0 = make_float2(acc[mt][nt][0], acc[mt][nt][1]);
            float2 v1 = make_float2(acc[mt][nt][2], acc[mt][nt][3]);
            if (BIAS) {
                float b0 = bias[nc], b1 = bias[nc + 1];
                v0.x += b0; v0.y += b1;
                v1.x += b0; v1.y += b1;
            }
            *(float2*)(C + m0 * Nc + nc)       = v0;
            *(float2*)(C + (m0 + 8) * Nc + nc) = v1;
        }
    }
#undef ST
}

// ---------------- LN(k), LN(v), q /= size[batch[n]] (in place on g_qkv) ----
__global__ __launch_bounds__(256)
void ln_scale_kernel(const int* __restrict__ batch,
                     const float* __restrict__ ln1w, const float* __restrict__ ln1b,
                     const float* __restrict__ ln2w, const float* __restrict__ ln2b) {
    int warp = threadIdx.x >> 5, lane = threadIdx.x & 31;
    size_t task = (size_t)blockIdx.x * 8 + warp;
    int h = (int)(task & 7);
    size_t bn = task >> 3;
    int n = (int)(bn & (N_TOK - 1));
    float* base = g_qkv + bn * QKV3 + h * DH;

    float inv = 1.0f / (float)g_sizes[batch[n]];
    base[lane]      *= inv;
    base[lane + 32] *= inv;

#pragma unroll
    for (int part = 0; part < 2; part++) {
        float* p = base + 512 + part * 512;
        const float* w  = part ? ln2w : ln1w;
        const float* bb = part ? ln2b : ln1b;
        float a = p[lane], c = p[lane + 32];
        float s = a + c;
#pragma unroll
        for (int o = 16; o; o >>= 1) s += __shfl_xor_sync(0xffffffffu, s, o);
        float mu = s * (1.0f / 64.0f);
        float d0 = a - mu, d1 = c - mu;
        float vv = d0 * d0 + d1 * d1;
#pragma unroll
        for (int o = 16; o; o >>= 1) vv += __shfl_xor_sync(0xffffffffu, vv, o);
        float rs = rsqrtf(vv * (1.0f / 64.0f) + 1e-6f);
        p[lane]      = d0 * rs * w[lane]      + bb[lane];
        p[lane + 32] = d1 * rs * w[lane + 32] + bb[lane + 32];
    }
}

// ---------------- ktv[b,h,g] = K_segT @ V_seg (64x64) -----------------------
__global__ __launch_bounds__(256)
void ktv_kernel() {
    int g = blockIdx.x & 31;
    int h = (blockIdx.x >> 5) & 7;
    int b = blockIdx.x >> 8;
    int s0 = g_off[g], s1 = g_off[g + 1];

    __shared__ __align__(16) float sk[32][64];
    __shared__ __align__(16) float sv[32][64];

    int tid = threadIdx.x;
    int ti = tid >> 3;
    int jb = (tid & 7) * 8;
    int i0 = (tid >> 4) * 4;
    int j0 = (tid & 15) * 4;

    float acc[4][4];
#pragma unroll
    for (int i = 0; i < 4; i++)
#pragma unroll
        for (int j = 0; j < 4; j++) acc[i][j] = 0.0f;

    for (int t0 = s0; t0 < s1; t0 += 32) {
        int n = t0 + ti;
        if (n < s1) {
            const float* row = g_qkv + ((size_t)b * N_TOK + n) * QKV3 + 512 + h * DH + jb;
            *(float4*)&sk[ti][jb]     = *(const float4*)(row);
            *(float4*)&sk[ti][jb + 4] = *(const float4*)(row + 4);
            *(float4*)&sv[ti][jb]     = *(const float4*)(row + 512);
            *(float4*)&sv[ti][jb + 4] = *(const float4*)(row + 516);
        } else {
            float4 z = make_float4(0.f, 0.f, 0.f, 0.f);
            *(float4*)&sk[ti][jb] = z; *(float4*)&sk[ti][jb + 4] = z;
            *(float4*)&sv[ti][jb] = z; *(float4*)&sv[ti][jb + 4] = z;
        }
        __syncthreads();
#pragma unroll
        for (int t = 0; t < 32; t++) {
            float4 ka = *(float4*)&sk[t][i0];
            float4 vb = *(float4*)&sv[t][j0];
            acc[0][0] += ka.x * vb.x; acc[0][1] += ka.x * vb.y;
            acc[0][2] += ka.x * vb.z; acc[0][3] += ka.x * vb.w;
            acc[1][0] += ka.y * vb.x; acc[1][1] += ka.y * vb.y;
            acc[1][2] += ka.y * vb.z; acc[1][3] += ka.y * vb.w;
            acc[2][0] += ka.z * vb.x; acc[2][1] += ka.z * vb.y;
            acc[2][2] += ka.z * vb.z; acc[2][3] += ka.z * vb.w;
            acc[3][0] += ka.w * vb.x; acc[3][1] += ka.w * vb.y;
            acc[3][2] += ka.w * vb.z; acc[3][3] += ka.w * vb.w;
        }
        __syncthreads();
    }

    float* out = g_ktv + (size_t)blockIdx.x * DH * DH;
#pragma unroll
    for (int i = 0; i < 4; i++)
        *(float4*)&out[(i0 + i) * DH + j0] =
            make_float4(acc[i][0], acc[i][1], acc[i][2], acc[i][3]);
}

// ---------------- attn[n] = qn[n] @ ktv[batch[n]]  -> bf16 hi/lo ------------
__global__ __launch_bounds__(256)
void apply_kernel() {
    int g = blockIdx.x & 31;
    int h = (blockIdx.x >> 5) & 7;
    int b = blockIdx.x >> 8;
    int s0 = g_off[g], s1 = g_off[g + 1];

    __shared__ __align__(16) float kt[DH * DH];
    __shared__ __align__(16) float sq[64][68];

    int tid = threadIdx.x;
    const float* ktg = g_ktv + (size_t)blockIdx.x * DH * DH;
#pragma unroll
    for (int i = 0; i < 16; i++) kt[i * 256 + tid] = ktg[i * 256 + tid];

    int t_ld = tid >> 2;
    int j_ld = (tid & 3) * 16;
    int t0q  = (tid >> 4) * 4;
    int j0   = (tid & 15) * 4;

    for (int base = s0; base < s1; base += 64) {
        int n = base + t_ld;
        if (n < s1) {
            const float* qrow = g_qkv + ((size_t)b * N_TOK + n) * QKV3 + h * DH;
#pragma unroll
            for (int c = 0; c < 4; c++)
                *(float4*)&sq[t_ld][j_ld + c * 4] = *(const float4*)(qrow + j_ld + c * 4);
        } else {
            float4 z = make_float4(0.f, 0.f, 0.f, 0.f);
#pragma unroll
            for (int c = 0; c < 4; c++) *(float4*)&sq[t_ld][j_ld + c * 4] = z;
        }
        __syncthreads();

        float acc[4][4];
#pragma unroll
        for (int i = 0; i < 4; i++)
#pragma unroll
            for (int j = 0; j < 4; j++) acc[i][j] = 0.0f;

#pragma unroll
        for (int i = 0; i < DH; i++) {
            float4 kv = *(float4*)&kt[i * DH + j0];
            float q0 = sq[t0q + 0][i], q1 = sq[t0q + 1][i];
            float q2 = sq[t0q + 2][i], q3 = sq[t0q + 3][i];
            acc[0][0] += q0 * kv.x; acc[0][1] += q0 * kv.y;
            acc[0][2] += q0 * kv.z; acc[0][3] += q0 * kv.w;
            acc[1][0] += q1 * kv.x; acc[1][1] += q1 * kv.y;
            acc[1][2] += q1 * kv.z; acc[1][3] += q1 * kv.w;
            acc[2][0] += q2 * kv.x; acc[2][1] += q2 * kv.y;
            acc[2][2] += q2 * kv.z; acc[2][3] += q2 * kv.w;
            acc[3][0] += q3 * kv.x; acc[3][1] += q3 * kv.y;
            acc[3][2] += q3 * kv.z; acc[3][3] += q3 * kv.w;
        }
        __syncthreads();

#pragma unroll
        for (int tt = 0; tt < 4; tt++) {
            int n2 = base + t0q + tt;
            if (n2 < s1) {
                size_t eidx = ((size_t)b * N_TOK + n2) * DIM + h * DH + j0;
                ushort4 vh, vl;
#pragma unroll
                for (int jj = 0; jj < 4; jj++) {
                    float f = acc[tt][jj];
                    __nv_bfloat16 hb = __float2bfloat16_rn(f);
                    __nv_bfloat16 lb = __float2bfloat16_rn(f - __bfloat162float(hb));
                    ((unsigned short*)&vh)[jj] = __bfloat16_as_ushort(hb);
                    ((unsigned short*)&vl)[jj] = __bfloat16_as_ushort(lb);
                }
                *(ushort4*)((unsigned short*)g_attn_hi + eidx) = vh;
                *(ushort4*)((unsigned short*)g_attn_lo + eidx) = vl;
            }
        }
    }
}

// ---------------- launch ----------------------------------------------------
extern "C" void kernel_launch(void* const* d_in, const int* in_sizes, int n_in,
                              void* d_out, int out_size) {
    const float* x     = (const float*)d_in[0];
    const float* w_qkv = (const float*)d_in[1];
    const float* ln1w  = (const float*)d_in[2];
    const float* ln1b  = (const float*)d_in[3];
    const float* ln2w  = (const float*)d_in[4];
    const float* ln2b  = (const float*)d_in[5];
    const float* w_out = (const float*)d_in[6];
    const float* b_out = (const float*)d_in[7];
    const int*   batch = (const int*)d_in[8];
    float* out = (float*)d_out;

    float *qkv_p;
    __nv_bfloat16 *ah_p, *al_p, *b1h_p, *b1l_p, *b2h_p, *b2l_p, *ath_p, *atl_p;
    cudaGetSymbolAddress((void**)&qkv_p, g_qkv);
    cudaGetSymbolAddress((void**)&ah_p,  g_a_hi);
    cudaGetSymbolAddress((void**)&al_p,  g_a_lo);
    cudaGetSymbolAddress((void**)&b1h_p, g_b1_hi);
    cudaGetSymbolAddress((void**)&b1l_p, g_b1_lo);
    cudaGetSymbolAddress((void**)&b2h_p, g_b2_hi);
    cudaGetSymbolAddress((void**)&b2l_p, g_b2_lo);
    cudaGetSymbolAddress((void**)&ath_p, g_attn_hi);
    cudaGetSymbolAddress((void**)&atl_p, g_attn_lo);

    cudaFuncSetAttribute(mgemm_kernel<false>, cudaFuncAttributeMaxDynamicSharedMemorySize, MG_SMEM);
    cudaFuncSetAttribute(mgemm_kernel<true>,  cudaFuncAttributeMaxDynamicSharedMemorySize, MG_SMEM);

    // 0) segment offsets
    hist_kernel<<<1, 256>>>(batch);

    // 1) fp32 -> bf16 hi/lo splits
    conv_split_kernel<<<4096, 256>>>(x,     ah_p,  al_p,  (long)M_ROWS * KDIM / 4);
    conv_split_kernel<<<512,  256>>>(w_qkv, b1h_p, b1l_p, (long)QKV3 * KDIM / 4);
    conv_split_kernel<<<256,  256>>>(w_out, b2h_p, b2l_p, (long)DIM * KDIM / 4);

    // 2) qkv = x @ w_qkvT  (mma.sync split-bf16)
    mgemm_kernel<false><<<dim3(QKV3 / 128, M_ROWS / 128), 256, MG_SMEM>>>(
        ah_p, al_p, b1h_p, b1l_p, qkv_p, nullptr, QKV3);

    // 3) LN(k), LN(v), q scaling
    ln_scale_kernel<<<(M_ROWS * HEADS) / 8, 256>>>(batch, ln1w, ln1b, ln2w, ln2b);

    // 4) ktv per (b,h,g)
    ktv_kernel<<<B_SZ * HEADS * NGRAPH, 256>>>();

    // 5) attn = qn @ ktv[seg]  -> bf16 hi/lo
    apply_kernel<<<B_SZ * HEADS * NGRAPH, 256>>>();

    // 6) out = attn @ w_outT + b_out  (mma.sync split-bf16)
    mgemm_kernel<true><<<dim3(DIM / 128, M_ROWS / 128), 256, MG_SMEM>>>(
        ath_p, atl_p, b2h_p, b2l_p, out, b_out, DIM);
}

// round 4
// speedup vs baseline: 2.4534x; 1.1254x over previous
#include <cuda_runtime.h>
#include <cuda_fp16.h>
#include <cstdint>

// ---------------- problem constants (fixed by setup_inputs) ----------------
#define B_SZ   2
#define N_TOK  32768
#define DIM    512
#define HEADS  8
#define DH     64
#define NGRAPH 32
#define QKV3   1536
#define M_ROWS (B_SZ * N_TOK)          // 65536
#define KDIM   512

// ---------------- device scratch (static; no allocations allowed) ----------
__device__ float  g_qkv [(size_t)M_ROWS * QKV3];
__device__ __half g_a_hi[(size_t)M_ROWS * KDIM];
__device__ __half g_a_lo[(size_t)M_ROWS * KDIM];
__device__ __half g_b1_hi[QKV3 * KDIM];
__device__ __half g_b1_lo[QKV3 * KDIM];
__device__ __half g_b2_hi[DIM * KDIM];
__device__ __half g_b2_lo[DIM * KDIM];
__device__ __half g_attn_hi[(size_t)M_ROWS * DIM];
__device__ __half g_attn_lo[(size_t)M_ROWS * DIM];
__device__ float  g_ktv[B_SZ * HEADS * NGRAPH * DH * DH];
__device__ int    g_sizes[NGRAPH];
__device__ int    g_off [NGRAPH + 1];

// ---------------- helpers ---------------------------------------------------
__device__ __forceinline__ uint32_t smem_u32(const void* p) {
    uint32_t a;
    asm("{ .reg .u64 t; cvta.to.shared.u64 t, %1; cvt.u32.u64 %0, t; }"
        : "=r"(a) : "l"(p));
    return a;
}
__device__ __forceinline__ uint32_t lds32(uint32_t a) {
    uint32_t v;
    asm("ld.shared.b32 %0, [%1];" : "=r"(v) : "r"(a));
    return v;
}
__device__ __forceinline__ void mma16816(float* d, const uint32_t* a, const uint32_t* b) {
    asm volatile(
        "mma.sync.aligned.m16n8k16.row.col.f32.f16.f16.f32 "
        "{%0,%1,%2,%3}, {%4,%5,%6,%7}, {%8,%9}, {%0,%1,%2,%3};"
        : "+f"(d[0]), "+f"(d[1]), "+f"(d[2]), "+f"(d[3])
        : "r"(a[0]), "r"(a[1]), "r"(a[2]), "r"(a[3]), "r"(b[0]), "r"(b[1]));
}

// ---------------- small kernels ---------------------------------------------
__global__ void hist_kernel(const int* __restrict__ batch) {
    __shared__ int cnt[NGRAPH];
    int tid = threadIdx.x;
    if (tid < NGRAPH) cnt[tid] = 0;
    __syncthreads();
    for (int i = tid; i < N_TOK; i += 256) atomicAdd(&cnt[batch[i]], 1);
    __syncthreads();
    if (tid == 0) {
        int off = 0;
        for (int g = 0; g < NGRAPH; g++) {
            g_off[g] = off; g_sizes[g] = cnt[g]; off += cnt[g];
        }
        g_off[NGRAPH] = off;
    }
}

__device__ __forceinline__ void split4(float4 v, ushort4& vh, ushort4& vl) {
    __half h0 = __float2half_rn(v.x), h1 = __float2half_rn(v.y);
    __half h2 = __float2half_rn(v.z), h3 = __float2half_rn(v.w);
    __half l0 = __float2half_rn(v.x - __half2float(h0));
    __half l1 = __float2half_rn(v.y - __half2float(h1));
    __half l2 = __float2half_rn(v.z - __half2float(h2));
    __half l3 = __float2half_rn(v.w - __half2float(h3));
    vh.x = __half_as_ushort(h0); vh.y = __half_as_ushort(h1);
    vh.z = __half_as_ushort(h2); vh.w = __half_as_ushort(h3);
    vl.x = __half_as_ushort(l0); vl.y = __half_as_ushort(l1);
    vl.z = __half_as_ushort(l2); vl.w = __half_as_ushort(l3);
}

// fp32 -> (fp16 hi, fp16 lo) split, x4
__global__ void conv_split_kernel(const float* __restrict__ src,
                                  __half* __restrict__ hi,
                                  __half* __restrict__ lo, long n4) {
    long i = (long)blockIdx.x * blockDim.x + threadIdx.x;
    long stride = (long)gridDim.x * blockDim.x;
    for (; i < n4; i += stride) {
        ushort4 vh, vl;
        split4(((const float4*)src)[i], vh, vl);
        ((ushort4*)hi)[i] = vh;
        ((ushort4*)lo)[i] = vl;
    }
}

// both weight matrices in one launch
__global__ void conv_w_kernel(const float* __restrict__ w1,
                              const float* __restrict__ w2) {
    const long n1 = (long)QKV3 * KDIM / 4;
    const long n2 = (long)DIM * KDIM / 4;
    long i = (long)blockIdx.x * blockDim.x + threadIdx.x;
    long stride = (long)gridDim.x * blockDim.x;
    for (; i < n1 + n2; i += stride) {
        ushort4 vh, vl;
        if (i < n1) {
            split4(((const float4*)w1)[i], vh, vl);
            ((ushort4*)g_b1_hi)[i] = vh;
            ((ushort4*)g_b1_lo)[i] = vl;
        } else {
            long j = i - n1;
            split4(((const float4*)w2)[j], vh, vl);
            ((ushort4*)g_b2_hi)[j] = vh;
            ((ushort4*)g_b2_lo)[j] = vl;
        }
    }
}

// ---------------- mma.sync split-fp16 GEMM ----------------------------------
// MODE 0: qkv = x @ w_qkvT, 3-term, fused LN/scale epilogue, Nc=1536
// MODE 1: out = attn @ w_outT + bias, 2-term ((Ah+Al)*Bh), Nc=512
#define STRW 36                     // smem row stride in 32-bit words
#define TEN_BYTES (128 * 144)

__device__ __forceinline__ void issue_slab(uint32_t sdst, const __half* g,
                                           int k0, int tid) {
#pragma unroll
    for (int t = 0; t < 4; t++) {
        int id  = tid + t * 256;
        int row = id >> 3, col = id & 7;
        uint32_t s = sdst + row * 144 + col * 16;
        const void* gp = g + (size_t)row * KDIM + k0 + col * 8;
        asm volatile("cp.async.cg.shared.global [%0], [%1], 16;" :: "r"(s), "l"(gp));
    }
}

template <int MODE>
__global__ __launch_bounds__(256)
void mgemm_kernel(const __half* __restrict__ Ah, const __half* __restrict__ Al,
                  const __half* __restrict__ Bh, const __half* __restrict__ Bl,
                  float* __restrict__ C, const float* __restrict__ bias,
                  const int* __restrict__ batch,
                  const float* __restrict__ ln1w, const float* __restrict__ ln1b,
                  const float* __restrict__ ln2w, const float* __restrict__ ln2b) {
    constexpr int NSLAB = (MODE == 0) ? 4 : 3;   // Ah, Al, Bh (+Bl for 3-term)
    constexpr int NC    = (MODE == 0) ? QKV3 : DIM;
    extern __shared__ __align__(16) char smem[];
    uint32_t sb = smem_u32(smem);
    int tid = threadIdx.x, wid = tid >> 5, lane = tid & 31;
    int warpM = (wid & 3) * 32;
    int warpN = (wid >> 2) * 64;

    const __half* pAh = Ah + (size_t)blockIdx.y * 128 * KDIM;
    const __half* pAl = Al + (size_t)blockIdx.y * 128 * KDIM;
    const __half* pBh = Bh + (size_t)blockIdx.x * 128 * KDIM;
    const __half* pBl = Bl + (size_t)blockIdx.x * 128 * KDIM;

#define ST(s, t) (sb + ((s) * NSLAB + (t)) * TEN_BYTES)

#define ISSUE_STAGE(s, k0)                                   \
    do {                                                     \
        issue_slab(ST(s, 0), pAh, (k0), tid);                \
        issue_slab(ST(s, 1), pAl, (k0), tid);                \
        issue_slab(ST(s, 2), pBh, (k0), tid);                \
        if (MODE == 0) issue_slab(ST(s, 3), pBl, (k0), tid); \
        asm volatile("cp.async.commit_group;");              \
    } while (0)

    ISSUE_STAGE(0, 0);
    ISSUE_STAGE(1, 64);

    float acc[2][8][4];
#pragma unroll
    for (int i = 0; i < 2; i++)
#pragma unroll
        for (int j = 0; j < 8; j++)
#pragma unroll
            for (int k = 0; k < 4; k++) acc[i][j][k] = 0.0f;

    int g = lane >> 2, c2 = lane & 3;

    for (int it = 0; it < 8; it++) {
        int s = it & 1;
        if (it < 7) asm volatile("cp.async.wait_group 1;");
        else        asm volatile("cp.async.wait_group 0;");
        __syncthreads();
        uint32_t sAh = ST(s, 0), sAl = ST(s, 1), sBh = ST(s, 2), sBl = ST(s, 3);
#pragma unroll
        for (int kk = 0; kk < 4; kk++) {
            int kw = kk * 8 + c2;
            uint32_t ah[2][4], al[2][4], bh[8][2], bl[8][2];
#pragma unroll
            for (int mt = 0; mt < 2; mt++) {
                uint32_t o0 = ((warpM + mt * 16 + g) * STRW + kw) * 4;
                uint32_t o1 = o0 + 8 * STRW * 4;
                ah[mt][0] = lds32(sAh + o0);      ah[mt][1] = lds32(sAh + o1);
                ah[mt][2] = lds32(sAh + o0 + 16); ah[mt][3] = lds32(sAh + o1 + 16);
                al[mt][0] = lds32(sAl + o0);      al[mt][1] = lds32(sAl + o1);
                al[mt][2] = lds32(sAl + o0 + 16); al[mt][3] = lds32(sAl + o1 + 16);
            }
#pragma unroll
            for (int nt = 0; nt < 8; nt++) {
                uint32_t o = ((warpN + nt * 8 + g) * STRW + kw) * 4;
                bh[nt][0] = lds32(sBh + o); bh[nt][1] = lds32(sBh + o + 16);
                if (MODE == 0) {
                    bl[nt][0] = lds32(sBl + o); bl[nt][1] = lds32(sBl + o + 16);
                }
            }
#pragma unroll
            for (int mt = 0; mt < 2; mt++)
#pragma unroll
                for (int nt = 0; nt < 8; nt++) {
                    mma16816(acc[mt][nt], ah[mt], bh[nt]);
                    mma16816(acc[mt][nt], al[mt], bh[nt]);
                    if (MODE == 0) mma16816(acc[mt][nt], ah[mt], bl[nt]);
                }
        }
        __syncthreads();
        if (it + 2 < 8) ISSUE_STAGE(s, (it + 2) * 64);
    }

    // ---------------- epilogue ----------------
    if (MODE == 1) {
#pragma unroll
        for (int mt = 0; mt < 2; mt++) {
            size_t m0 = (size_t)blockIdx.y * 128 + warpM + mt * 16 + g;
#pragma unroll
            for (int nt = 0; nt < 8; nt++) {
                int nc = blockIdx.x * 128 + warpN + nt * 8 + c2 * 2;
                float b0 = bias[nc], b1 = bias[nc + 1];
                *(float2*)(C + m0 * NC + nc) =
                    make_float2(acc[mt][nt][0] + b0, acc[mt][nt][1] + b1);
                *(float2*)(C + (m0 + 8) * NC + nc) =
                    make_float2(acc[mt][nt][2] + b0, acc[mt][nt][3] + b1);
            }
        }
    } else {
        // fused: q /= size[batch[n]]; LN(k) with ln1; LN(v) with ln2
        int mode = blockIdx.x >> 2;          // 0..3 q, 4..7 k, 8..11 v
        const float* lw = (mode == 1) ? ln1w : ln2w;
        const float* lb = (mode == 1) ? ln1b : ln2b;
#pragma unroll
        for (int mt = 0; mt < 2; mt++) {
#pragma unroll
            for (int hf = 0; hf < 2; hf++) {
                size_t m = (size_t)blockIdx.y * 128 + warpM + mt * 16 + g + hf * 8;
                float v[16];
#pragma unroll
                for (int nt = 0; nt < 8; nt++) {
                    v[nt * 2]     = acc[mt][nt][hf * 2];
                    v[nt * 2 + 1] = acc[mt][nt][hf * 2 + 1];
                }
                if (mode == 0) {
                    int n = (int)(m & (N_TOK - 1));
                    float sc = 1.0f / (float)g_sizes[batch[n]];
#pragma unroll
                    for (int k = 0; k < 16; k++) v[k] *= sc;
                } else {
                    float s = 0.f, s2 = 0.f;
#pragma unroll
                    for (int k = 0; k < 16; k++) { s += v[k]; s2 += v[k] * v[k]; }
                    s  += __shfl_xor_sync(0xffffffffu, s, 1);
                    s  += __shfl_xor_sync(0xffffffffu, s, 2);
                    s2 += __shfl_xor_sync(0xffffffffu, s2, 1);
                    s2 += __shfl_xor_sync(0xffffffffu, s2, 2);
                    float mu = s * (1.0f / 64.0f);
                    float var = s2 * (1.0f / 64.0f) - mu * mu;
                    float rs = rsqrtf(var + 1e-6f);
#pragma unroll
                    for (int nt = 0; nt < 8; nt++) {
#pragma unroll
                        for (int j = 0; j < 2; j++) {
                            int cl = nt * 8 + c2 * 2 + j;   // head-local col
                            v[nt * 2 + j] = (v[nt * 2 + j] - mu) * rs * lw[cl] + lb[cl];
                        }
                    }
                }
                float* cp = C + m * NC + blockIdx.x * 128 + warpN;
#pragma unroll
                for (int nt = 0; nt < 8; nt++)
                    *(float2*)(cp + nt * 8 + c2 * 2) = make_float2(v[nt * 2], v[nt * 2 + 1]);
            }
        }
    }
#undef ST
#undef ISSUE_STAGE
}

// ---------------- ktv[b,h,g] = K_segT @ V_seg (64x64) -----------------------
__global__ __launch_bounds__(256)
void ktv_kernel() {
    int g = blockIdx.x & 31;
    int h = (blockIdx.x >> 5) & 7;
    int b = blockIdx.x >> 8;
    int s0 = g_off[g], s1 = g_off[g + 1];

    __shared__ __align__(16) float sk[32][64];
    __shared__ __align__(16) float sv[32][64];

    int tid = threadIdx.x;
    int ti = tid >> 3;
    int jb = (tid & 7) * 8;
    int i0 = (tid >> 4) * 4;
    int j0 = (tid & 15) * 4;

    float acc[4][4];
#pragma unroll
    for (int i = 0; i < 4; i++)
#pragma unroll
        for (int j = 0; j < 4; j++) acc[i][j] = 0.0f;

    for (int t0 = s0; t0 < s1; t0 += 32) {
        int n = t0 + ti;
        if (n < s1) {
            const float* row = g_qkv + ((size_t)b * N_TOK + n) * QKV3 + 512 + h * DH + jb;
            *(float4*)&sk[ti][jb]     = *(const float4*)(row);
            *(float4*)&sk[ti][jb + 4] = *(const float4*)(row + 4);
            *(float4*)&sv[ti][jb]     = *(const float4*)(row + 512);
            *(float4*)&sv[ti][jb + 4] = *(const float4*)(row + 516);
        } else {
            float4 z = make_float4(0.f, 0.f, 0.f, 0.f);
            *(float4*)&sk[ti][jb] = z; *(float4*)&sk[ti][jb + 4] = z;
            *(float4*)&sv[ti][jb] = z; *(float4*)&sv[ti][jb + 4] = z;
        }
        __syncthreads();
#pragma unroll
        for (int t = 0; t < 32; t++) {
            float4 ka = *(float4*)&sk[t][i0];
            float4 vb = *(float4*)&sv[t][j0];
            acc[0][0] += ka.x * vb.x; acc[0][1] += ka.x * vb.y;
            acc[0][2] += ka.x * vb.z; acc[0][3] += ka.x * vb.w;
            acc[1][0] += ka.y * vb.x; acc[1][1] += ka.y * vb.y;
            acc[1][2] += ka.y * vb.z; acc[1][3] += ka.y * vb.w;
            acc[2][0] += ka.z * vb.x; acc[2][1] += ka.z * vb.y;
            acc[2][2] += ka.z * vb.z; acc[2][3] += ka.z * vb.w;
            acc[3][0] += ka.w * vb.x; acc[3][1] += ka.w * vb.y;
            acc[3][2] += ka.w * vb.z; acc[3][3] += ka.w * vb.w;
        }
        __syncthreads();
    }

    float* out = g_ktv + (size_t)blockIdx.x * DH * DH;
#pragma unroll
    for (int i = 0; i < 4; i++)
        *(float4*)&out[(i0 + i) * DH + j0] =
            make_float4(acc[i][0], acc[i][1], acc[i][2], acc[i][3]);
}

// ---------------- attn[n] = qn[n] @ ktv[batch[n]]  -> fp16 hi/lo ------------
__global__ __launch_bounds__(256)
void apply_kernel() {
    int g = blockIdx.x & 31;
    int h = (blockIdx.x >> 5) & 7;
    int b = blockIdx.x >> 8;
    int s0 = g_off[g], s1 = g_off[g + 1];

    __shared__ __align__(16) float kt[DH * DH];
    __shared__ __align__(16) float sq[64][68];

    int tid = threadIdx.x;
    const float* ktg = g_ktv + (size_t)blockIdx.x * DH * DH;
#pragma unroll
    for (int i = 0; i < 16; i++) kt[i * 256 + tid] = ktg[i * 256 + tid];

    int t_ld = tid >> 2;
    int j_ld = (tid & 3) * 16;
    int t0q  = (tid >> 4) * 4;
    int j0   = (tid & 15) * 4;

    for (int base = s0; base < s1; base += 64) {
        int n = base + t_ld;
        if (n < s1) {
            const float* qrow = g_qkv + ((size_t)b * N_TOK + n) * QKV3 + h * DH;
#pragma unroll
            for (int c = 0; c < 4; c++)
                *(float4*)&sq[t_ld][j_ld + c * 4] = *(const float4*)(qrow + j_ld + c * 4);
        } else {
            float4 z = make_float4(0.f, 0.f, 0.f, 0.f);
#pragma unroll
            for (int c = 0; c < 4; c++) *(float4*)&sq[t_ld][j_ld + c * 4] = z;
        }
        __syncthreads();

        float acc[4][4];
#pragma unroll
        for (int i = 0; i < 4; i++)
#pragma unroll
            for (int j = 0; j < 4; j++) acc[i][j] = 0.0f;

#pragma unroll
        for (int i = 0; i < DH; i++) {
            float4 kv = *(float4*)&kt[i * DH + j0];
            float q0 = sq[t0q + 0][i], q1 = sq[t0q + 1][i];
            float q2 = sq[t0q + 2][i], q3 = sq[t0q + 3][i];
            acc[0][0] += q0 * kv.x; acc[0][1] += q0 * kv.y;
            acc[0][2] += q0 * kv.z; acc[0][3] += q0 * kv.w;
            acc[1][0] += q1 * kv.x; acc[1][1] += q1 * kv.y;
            acc[1][2] += q1 * kv.z; acc[1][3] += q1 * kv.w;
            acc[2][0] += q2 * kv.x; acc[2][1] += q2 * kv.y;
            acc[2][2] += q2 * kv.z; acc[2][3] += q2 * kv.w;
            acc[3][0] += q3 * kv.x; acc[3][1] += q3 * kv.y;
            acc[3][2] += q3 * kv.z; acc[3][3] += q3 * kv.w;
        }
        __syncthreads();

#pragma unroll
        for (int tt = 0; tt < 4; tt++) {
            int n2 = base + t0q + tt;
            if (n2 < s1) {
                size_t eidx = ((size_t)b * N_TOK + n2) * DIM + h * DH + j0;
                ushort4 vh, vl;
                float4 f = make_float4(acc[tt][0], acc[tt][1], acc[tt][2], acc[tt][3]);
                split4(f, vh, vl);
                *(ushort4*)((unsigned short*)g_attn_hi + eidx) = vh;
                *(ushort4*)((unsigned short*)g_attn_lo + eidx) = vl;
            }
        }
    }
}

// ---------------- launch ----------------------------------------------------
extern "C" void kernel_launch(void* const* d_in, const int* in_sizes, int n_in,
                              void* d_out, int out_size) {
    const float* x     = (const float*)d_in[0];
    const float* w_qkv = (const float*)d_in[1];
    const float* ln1w  = (const float*)d_in[2];
    const float* ln1b  = (const float*)d_in[3];
    const float* ln2w  = (const float*)d_in[4];
    const float* ln2b  = (const float*)d_in[5];
    const float* w_out = (const float*)d_in[6];
    const float* b_out = (const float*)d_in[7];
    const int*   batch = (const int*)d_in[8];
    float* out = (float*)d_out;

    float* qkv_p;
    __half *ah_p, *al_p, *b1h_p, *b1l_p, *b2h_p, *ath_p, *atl_p;
    cudaGetSymbolAddress((void**)&qkv_p, g_qkv);
    cudaGetSymbolAddress((void**)&ah_p,  g_a_hi);
    cudaGetSymbolAddress((void**)&al_p,  g_a_lo);
    cudaGetSymbolAddress((void**)&b1h_p, g_b1_hi);
    cudaGetSymbolAddress((void**)&b1l_p, g_b1_lo);
    cudaGetSymbolAddress((void**)&b2h_p, g_b2_hi);
    cudaGetSymbolAddress((void**)&ath_p, g_attn_hi);
    cudaGetSymbolAddress((void**)&atl_p, g_attn_lo);

    const int SMEM0 = 2 * 4 * TEN_BYTES;    // 147456
    const int SMEM1 = 2 * 3 * TEN_BYTES;    // 110592
    cudaFuncSetAttribute(mgemm_kernel<0>, cudaFuncAttributeMaxDynamicSharedMemorySize, SMEM0);
    cudaFuncSetAttribute(mgemm_kernel<1>, cudaFuncAttributeMaxDynamicSharedMemorySize, SMEM1);

    // 0) segment offsets (GEMM1 epilogue needs g_sizes)
    hist_kernel<<<1, 256>>>(batch);

    // 1) conversions
    conv_split_kernel<<<4096, 256>>>(x, ah_p, al_p, (long)M_ROWS * KDIM / 4);
    conv_w_kernel<<<1024, 256>>>(w_qkv, w_out);

    // 2) qkv = x @ w_qkvT (3-term) + fused LN/scale epilogue  [profiled launch]
    mgemm_kernel<0><<<dim3(QKV3 / 128, M_ROWS / 128), 256, SMEM0>>>(
        ah_p, al_p, b1h_p, b1l_p, qkv_p, nullptr, batch, ln1w, ln1b, ln2w, ln2b);

    // 3) ktv per (b,h,g)
    ktv_kernel<<<B_SZ * HEADS * NGRAPH, 256>>>();

    // 4) attn = qn @ ktv[seg] -> fp16 hi/lo
    apply_kernel<<<B_SZ * HEADS * NGRAPH, 256>>>();

    // 5) out = attn @ w_outT + b_out (2-term)
    mgemm_kernel<1><<<dim3(DIM / 128, M_ROWS / 128), 256, SMEM1>>>(
        ath_p, atl_p, b2h_p, nullptr, out, b_out, nullptr, nullptr, nullptr, nullptr, nullptr);
}

// round 5
// speedup vs baseline: 3.2231x; 1.3137x over previous
#include <cuda_runtime.h>
#include <cuda_fp16.h>
#include <cstdint>

// ---------------- problem constants (fixed by setup_inputs) ----------------
#define B_SZ   2
#define N_TOK  32768
#define DIM    512
#define HEADS  8
#define DH     64
#define NGRAPH 32
#define QKV3   1536
#define M_ROWS (B_SZ * N_TOK)          // 65536
#define KDIM   512

// ---------------- device scratch (static; no allocations allowed) ----------
__device__ float  g_qkv [(size_t)M_ROWS * QKV3];
__device__ __half g_a_hi[(size_t)M_ROWS * KDIM];
__device__ __half g_a_lo[(size_t)M_ROWS * KDIM];
__device__ __half g_b1_hi[QKV3 * KDIM];
__device__ __half g_b2_hi[DIM * KDIM];
__device__ __half g_attn_hi[(size_t)M_ROWS * DIM];
__device__ __half g_attn_lo[(size_t)M_ROWS * DIM];
__device__ float  g_ktv[B_SZ * HEADS * NGRAPH * DH * DH];
__device__ int    g_sizes[NGRAPH];
__device__ int    g_off [NGRAPH + 1];

// ---------------- helpers ---------------------------------------------------
__device__ __forceinline__ uint32_t smem_u32(const void* p) {
    uint32_t a;
    asm("{ .reg .u64 t; cvta.to.shared.u64 t, %1; cvt.u32.u64 %0, t; }"
        : "=r"(a) : "l"(p));
    return a;
}
__device__ __forceinline__ uint32_t lds32(uint32_t a) {
    uint32_t v;
    asm("ld.shared.b32 %0, [%1];" : "=r"(v) : "r"(a));
    return v;
}
__device__ __forceinline__ void mma16816(float* d, const uint32_t* a, const uint32_t* b) {
    asm volatile(
        "mma.sync.aligned.m16n8k16.row.col.f32.f16.f16.f32 "
        "{%0,%1,%2,%3}, {%4,%5,%6,%7}, {%8,%9}, {%0,%1,%2,%3};"
        : "+f"(d[0]), "+f"(d[1]), "+f"(d[2]), "+f"(d[3])
        : "r"(a[0]), "r"(a[1]), "r"(a[2]), "r"(a[3]), "r"(b[0]), "r"(b[1]));
}

// ---------------- small kernels ---------------------------------------------
__global__ void hist_kernel(const int* __restrict__ batch) {
    __shared__ int cnt[NGRAPH];
    int tid = threadIdx.x;
    if (tid < NGRAPH) cnt[tid] = 0;
    __syncthreads();
    for (int i = tid; i < N_TOK; i += 256) atomicAdd(&cnt[batch[i]], 1);
    __syncthreads();
    if (tid == 0) {
        int off = 0;
        for (int g = 0; g < NGRAPH; g++) {
            g_off[g] = off; g_sizes[g] = cnt[g]; off += cnt[g];
        }
        g_off[NGRAPH] = off;
    }
}

__device__ __forceinline__ void split4(float4 v, ushort4& vh, ushort4& vl) {
    __half h0 = __float2half_rn(v.x), h1 = __float2half_rn(v.y);
    __half h2 = __float2half_rn(v.z), h3 = __float2half_rn(v.w);
    __half l0 = __float2half_rn(v.x - __half2float(h0));
    __half l1 = __float2half_rn(v.y - __half2float(h1));
    __half l2 = __float2half_rn(v.z - __half2float(h2));
    __half l3 = __float2half_rn(v.w - __half2float(h3));
    vh.x = __half_as_ushort(h0); vh.y = __half_as_ushort(h1);
    vh.z = __half_as_ushort(h2); vh.w = __half_as_ushort(h3);
    vl.x = __half_as_ushort(l0); vl.y = __half_as_ushort(l1);
    vl.z = __half_as_ushort(l2); vl.w = __half_as_ushort(l3);
}
__device__ __forceinline__ ushort4 round4(float4 v) {
    ushort4 r;
    r.x = __half_as_ushort(__float2half_rn(v.x));
    r.y = __half_as_ushort(__float2half_rn(v.y));
    r.z = __half_as_ushort(__float2half_rn(v.z));
    r.w = __half_as_ushort(__float2half_rn(v.w));
    return r;
}

// fp32 -> (fp16 hi, fp16 lo) split, x4
__global__ void conv_split_kernel(const float* __restrict__ src,
                                  __half* __restrict__ hi,
                                  __half* __restrict__ lo, long n4) {
    long i = (long)blockIdx.x * blockDim.x + threadIdx.x;
    long stride = (long)gridDim.x * blockDim.x;
    for (; i < n4; i += stride) {
        ushort4 vh, vl;
        split4(((const float4*)src)[i], vh, vl);
        ((ushort4*)hi)[i] = vh;
        ((ushort4*)lo)[i] = vl;
    }
}

// both weight matrices, single-fp16 rounding, one launch
__global__ void conv_w_kernel(const float* __restrict__ w1,
                              const float* __restrict__ w2) {
    const long n1 = (long)QKV3 * KDIM / 4;
    const long n2 = (long)DIM * KDIM / 4;
    long i = (long)blockIdx.x * blockDim.x + threadIdx.x;
    long stride = (long)gridDim.x * blockDim.x;
    for (; i < n1 + n2; i += stride) {
        if (i < n1) ((ushort4*)g_b1_hi)[i]      = round4(((const float4*)w1)[i]);
        else        ((ushort4*)g_b2_hi)[i - n1] = round4(((const float4*)w2)[i - n1]);
    }
}

// ---------------- mma.sync split-fp16 GEMM (2-term: (Ah+Al)@Bh) -------------
// MODE 0: qkv = x @ w_qkvT, fused LN/scale epilogue, Nc=1536
// MODE 1: out = attn @ w_outT + bias, Nc=512
#define STRW 36                     // smem row stride in 32-bit words
#define TEN_BYTES (128 * 144)
#define MG_SMEM (2 * 3 * TEN_BYTES) // 110592 -> 2 CTAs/SM

__device__ __forceinline__ void issue_slab(uint32_t sdst, const __half* g,
                                           int k0, int tid) {
#pragma unroll
    for (int t = 0; t < 4; t++) {
        int id  = tid + t * 256;
        int row = id >> 3, col = id & 7;
        uint32_t s = sdst + row * 144 + col * 16;
        const void* gp = g + (size_t)row * KDIM + k0 + col * 8;
        asm volatile("cp.async.cg.shared.global [%0], [%1], 16;" :: "r"(s), "l"(gp));
    }
}

template <int MODE>
__global__ __launch_bounds__(256, 2)
void mgemm_kernel(const __half* __restrict__ Ah, const __half* __restrict__ Al,
                  const __half* __restrict__ Bh,
                  float* __restrict__ C, const float* __restrict__ bias,
                  const int* __restrict__ batch,
                  const float* __restrict__ ln1w, const float* __restrict__ ln1b,
                  const float* __restrict__ ln2w, const float* __restrict__ ln2b) {
    constexpr int NC = (MODE == 0) ? QKV3 : DIM;
    extern __shared__ __align__(16) char smem[];
    uint32_t sb = smem_u32(smem);
    int tid = threadIdx.x, wid = tid >> 5, lane = tid & 31;
    int warpM = (wid & 3) * 32;
    int warpN = (wid >> 2) * 64;

    const __half* pAh = Ah + (size_t)blockIdx.y * 128 * KDIM;
    const __half* pAl = Al + (size_t)blockIdx.y * 128 * KDIM;
    const __half* pBh = Bh + (size_t)blockIdx.x * 128 * KDIM;

#define ST(s, t) (sb + ((s) * 3 + (t)) * TEN_BYTES)
#define ISSUE_STAGE(s, k0)                        \
    do {                                          \
        issue_slab(ST(s, 0), pAh, (k0), tid);     \
        issue_slab(ST(s, 1), pAl, (k0), tid);     \
        issue_slab(ST(s, 2), pBh, (k0), tid);     \
        asm volatile("cp.async.commit_group;");   \
    } while (0)

    ISSUE_STAGE(0, 0);
    ISSUE_STAGE(1, 64);

    float acc[2][8][4];
#pragma unroll
    for (int i = 0; i < 2; i++)
#pragma unroll
        for (int j = 0; j < 8; j++)
#pragma unroll
            for (int k = 0; k < 4; k++) acc[i][j][k] = 0.0f;

    int g = lane >> 2, c2 = lane & 3;

    for (int it = 0; it < 8; it++) {
        int s = it & 1;
        if (it < 7) asm volatile("cp.async.wait_group 1;");
        else        asm volatile("cp.async.wait_group 0;");
        __syncthreads();
        uint32_t sAh = ST(s, 0), sAl = ST(s, 1), sBh = ST(s, 2);
#pragma unroll
        for (int kk = 0; kk < 4; kk++) {
            int kw = kk * 8 + c2;
            uint32_t ah[2][4], al[2][4], bh[8][2];
#pragma unroll
            for (int mt = 0; mt < 2; mt++) {
                uint32_t o0 = ((warpM + mt * 16 + g) * STRW + kw) * 4;
                uint32_t o1 = o0 + 8 * STRW * 4;
                ah[mt][0] = lds32(sAh + o0);      ah[mt][1] = lds32(sAh + o1);
                ah[mt][2] = lds32(sAh + o0 + 16); ah[mt][3] = lds32(sAh + o1 + 16);
                al[mt][0] = lds32(sAl + o0);      al[mt][1] = lds32(sAl + o1);
                al[mt][2] = lds32(sAl + o0 + 16); al[mt][3] = lds32(sAl + o1 + 16);
            }
#pragma unroll
            for (int nt = 0; nt < 8; nt++) {
                uint32_t o = ((warpN + nt * 8 + g) * STRW + kw) * 4;
                bh[nt][0] = lds32(sBh + o); bh[nt][1] = lds32(sBh + o + 16);
            }
#pragma unroll
            for (int mt = 0; mt < 2; mt++)
#pragma unroll
                for (int nt = 0; nt < 8; nt++) {
                    mma16816(acc[mt][nt], ah[mt], bh[nt]);
                    mma16816(acc[mt][nt], al[mt], bh[nt]);
                }
        }
        __syncthreads();
        if (it + 2 < 8) ISSUE_STAGE(s, (it + 2) * 64);
    }

    // ---------------- epilogue ----------------
    if (MODE == 1) {
#pragma unroll
        for (int mt = 0; mt < 2; mt++) {
            size_t m0 = (size_t)blockIdx.y * 128 + warpM + mt * 16 + g;
#pragma unroll
            for (int nt = 0; nt < 8; nt++) {
                int nc = blockIdx.x * 128 + warpN + nt * 8 + c2 * 2;
                float b0 = bias[nc], b1 = bias[nc + 1];
                *(float2*)(C + m0 * NC + nc) =
                    make_float2(acc[mt][nt][0] + b0, acc[mt][nt][1] + b1);
                *(float2*)(C + (m0 + 8) * NC + nc) =
                    make_float2(acc[mt][nt][2] + b0, acc[mt][nt][3] + b1);
            }
        }
    } else {
        // fused: q /= size[batch[n]]; LN(k) with ln1; LN(v) with ln2
        int mode = blockIdx.x >> 2;          // 0..3 q, 4..7 k, 8..11 v
        const float* lw = (mode == 1) ? ln1w : ln2w;
        const float* lb = (mode == 1) ? ln1b : ln2b;
#pragma unroll
        for (int mt = 0; mt < 2; mt++) {
#pragma unroll
            for (int hf = 0; hf < 2; hf++) {
                size_t m = (size_t)blockIdx.y * 128 + warpM + mt * 16 + g + hf * 8;
                float v[16];
#pragma unroll
                for (int nt = 0; nt < 8; nt++) {
                    v[nt * 2]     = acc[mt][nt][hf * 2];
                    v[nt * 2 + 1] = acc[mt][nt][hf * 2 + 1];
                }
                if (mode == 0) {
                    int n = (int)(m & (N_TOK - 1));
                    float sc = 1.0f / (float)g_sizes[batch[n]];
#pragma unroll
                    for (int k = 0; k < 16; k++) v[k] *= sc;
                } else {
                    float s = 0.f, s2 = 0.f;
#pragma unroll
                    for (int k = 0; k < 16; k++) { s += v[k]; s2 += v[k] * v[k]; }
                    s  += __shfl_xor_sync(0xffffffffu, s, 1);
                    s  += __shfl_xor_sync(0xffffffffu, s, 2);
                    s2 += __shfl_xor_sync(0xffffffffu, s2, 1);
                    s2 += __shfl_xor_sync(0xffffffffu, s2, 2);
                    float mu = s * (1.0f / 64.0f);
                    float var = s2 * (1.0f / 64.0f) - mu * mu;
                    float rs = rsqrtf(var + 1e-6f);
#pragma unroll
                    for (int nt = 0; nt < 8; nt++) {
#pragma unroll
                        for (int j = 0; j < 2; j++) {
                            int cl = nt * 8 + c2 * 2 + j;   // head-local col
                            v[nt * 2 + j] = (v[nt * 2 + j] - mu) * rs * lw[cl] + lb[cl];
                        }
                    }
                }
                float* cp = C + m * NC + blockIdx.x * 128 + warpN;
#pragma unroll
                for (int nt = 0; nt < 8; nt++)
                    *(float2*)(cp + nt * 8 + c2 * 2) = make_float2(v[nt * 2], v[nt * 2 + 1]);
            }
        }
    }
#undef ST
#undef ISSUE_STAGE
}

// ---------------- ktv[b,h,g] = K_segT @ V_seg (64x64) -----------------------
__global__ __launch_bounds__(256)
void ktv_kernel() {
    int g = blockIdx.x & 31;
    int h = (blockIdx.x >> 5) & 7;
    int b = blockIdx.x >> 8;
    int s0 = g_off[g], s1 = g_off[g + 1];

    __shared__ __align__(16) float sk[32][64];
    __shared__ __align__(16) float sv[32][64];

    int tid = threadIdx.x;
    int ti = tid >> 3;
    int jb = (tid & 7) * 8;
    int i0 = (tid >> 4) * 4;
    int j0 = (tid & 15) * 4;

    float acc[4][4];
#pragma unroll
    for (int i = 0; i < 4; i++)
#pragma unroll
        for (int j = 0; j < 4; j++) acc[i][j] = 0.0f;

    for (int t0 = s0; t0 < s1; t0 += 32) {
        int n = t0 + ti;
        if (n < s1) {
            const float* row = g_qkv + ((size_t)b * N_TOK + n) * QKV3 + 512 + h * DH + jb;
            *(float4*)&sk[ti][jb]     = *(const float4*)(row);
            *(float4*)&sk[ti][jb + 4] = *(const float4*)(row + 4);
            *(float4*)&sv[ti][jb]     = *(const float4*)(row + 512);
            *(float4*)&sv[ti][jb + 4] = *(const float4*)(row + 516);
        } else {
            float4 z = make_float4(0.f, 0.f, 0.f, 0.f);
            *(float4*)&sk[ti][jb] = z; *(float4*)&sk[ti][jb + 4] = z;
            *(float4*)&sv[ti][jb] = z; *(float4*)&sv[ti][jb + 4] = z;
        }
        __syncthreads();
#pragma unroll
        for (int t = 0; t < 32; t++) {
            float4 ka = *(float4*)&sk[t][i0];
            float4 vb = *(float4*)&sv[t][j0];
            acc[0][0] += ka.x * vb.x; acc[0][1] += ka.x * vb.y;
            acc[0][2] += ka.x * vb.z; acc[0][3] += ka.x * vb.w;
            acc[1][0] += ka.y * vb.x; acc[1][1] += ka.y * vb.y;
            acc[1][2] += ka.y * vb.z; acc[1][3] += ka.y * vb.w;
            acc[2][0] += ka.z * vb.x; acc[2][1] += ka.z * vb.y;
            acc[2][2] += ka.z * vb.z; acc[2][3] += ka.z * vb.w;
            acc[3][0] += ka.w * vb.x; acc[3][1] += ka.w * vb.y;
            acc[3][2] += ka.w * vb.z; acc[3][3] += ka.w * vb.w;
        }
        __syncthreads();
    }

    float* out = g_ktv + (size_t)blockIdx.x * DH * DH;
#pragma unroll
    for (int i = 0; i < 4; i++)
        *(float4*)&out[(i0 + i) * DH + j0] =
            make_float4(acc[i][0], acc[i][1], acc[i][2], acc[i][3]);
}

// ---------------- attn[n] = qn[n] @ ktv[batch[n]]  -> fp16 hi/lo ------------
__global__ __launch_bounds__(256)
void apply_kernel() {
    int g = blockIdx.x & 31;
    int h = (blockIdx.x >> 5) & 7;
    int b = blockIdx.x >> 8;
    int s0 = g_off[g], s1 = g_off[g + 1];

    __shared__ __align__(16) float kt[DH * DH];
    __shared__ __align__(16) float sq[64][68];

    int tid = threadIdx.x;
    const float* ktg = g_ktv + (size_t)blockIdx.x * DH * DH;
#pragma unroll
    for (int i = 0; i < 16; i++) kt[i * 256 + tid] = ktg[i * 256 + tid];

    int t_ld = tid >> 2;
    int j_ld = (tid & 3) * 16;
    int t0q  = (tid >> 4) * 4;
    int j0   = (tid & 15) * 4;

    for (int base = s0; base < s1; base += 64) {
        int n = base + t_ld;
        if (n < s1) {
            const float* qrow = g_qkv + ((size_t)b * N_TOK + n) * QKV3 + h * DH;
#pragma unroll
            for (int c = 0; c < 4; c++)
                *(float4*)&sq[t_ld][j_ld + c * 4] = *(const float4*)(qrow + j_ld + c * 4);
        } else {
            float4 z = make_float4(0.f, 0.f, 0.f, 0.f);
#pragma unroll
            for (int c = 0; c < 4; c++) *(float4*)&sq[t_ld][j_ld + c * 4] = z;
        }
        __syncthreads();

        float acc[4][4];
#pragma unroll
        for (int i = 0; i < 4; i++)
#pragma unroll
            for (int j = 0; j < 4; j++) acc[i][j] = 0.0f;

#pragma unroll
        for (int i = 0; i < DH; i++) {
            float4 kv = *(float4*)&kt[i * DH + j0];
            float q0 = sq[t0q + 0][i], q1 = sq[t0q + 1][i];
            float q2 = sq[t0q + 2][i], q3 = sq[t0q + 3][i];
            acc[0][0] += q0 * kv.x; acc[0][1] += q0 * kv.y;
            acc[0][2] += q0 * kv.z; acc[0][3] += q0 * kv.w;
            acc[1][0] += q1 * kv.x; acc[1][1] += q1 * kv.y;
            acc[1][2] += q1 * kv.z; acc[1][3] += q1 * kv.w;
            acc[2][0] += q2 * kv.x; acc[2][1] += q2 * kv.y;
            acc[2][2] += q2 * kv.z; acc[2][3] += q2 * kv.w;
            acc[3][0] += q3 * kv.x; acc[3][1] += q3 * kv.y;
            acc[3][2] += q3 * kv.z; acc[3][3] += q3 * kv.w;
        }
        __syncthreads();

#pragma unroll
        for (int tt = 0; tt < 4; tt++) {
            int n2 = base + t0q + tt;
            if (n2 < s1) {
                size_t eidx = ((size_t)b * N_TOK + n2) * DIM + h * DH + j0;
                ushort4 vh, vl;
                float4 f = make_float4(acc[tt][0], acc[tt][1], acc[tt][2], acc[tt][3]);
                split4(f, vh, vl);
                *(ushort4*)((unsigned short*)g_attn_hi + eidx) = vh;
                *(ushort4*)((unsigned short*)g_attn_lo + eidx) = vl;
            }
        }
    }
}

// ---------------- launch ----------------------------------------------------
extern "C" void kernel_launch(void* const* d_in, const int* in_sizes, int n_in,
                              void* d_out, int out_size) {
    const float* x     = (const float*)d_in[0];
    const float* w_qkv = (const float*)d_in[1];
    const float* ln1w  = (const float*)d_in[2];
    const float* ln1b  = (const float*)d_in[3];
    const float* ln2w  = (const float*)d_in[4];
    const float* ln2b  = (const float*)d_in[5];
    const float* w_out = (const float*)d_in[6];
    const float* b_out = (const float*)d_in[7];
    const int*   batch = (const int*)d_in[8];
    float* out = (float*)d_out;

    float* qkv_p;
    __half *ah_p, *al_p, *b1h_p, *b2h_p, *ath_p, *atl_p;
    cudaGetSymbolAddress((void**)&qkv_p, g_qkv);
    cudaGetSymbolAddress((void**)&ah_p,  g_a_hi);
    cudaGetSymbolAddress((void**)&al_p,  g_a_lo);
    cudaGetSymbolAddress((void**)&b1h_p, g_b1_hi);
    cudaGetSymbolAddress((void**)&b2h_p, g_b2_hi);
    cudaGetSymbolAddress((void**)&ath_p, g_attn_hi);
    cudaGetSymbolAddress((void**)&atl_p, g_attn_lo);

    cudaFuncSetAttribute(mgemm_kernel<0>, cudaFuncAttributeMaxDynamicSharedMemorySize, MG_SMEM);
    cudaFuncSetAttribute(mgemm_kernel<1>, cudaFuncAttributeMaxDynamicSharedMemorySize, MG_SMEM);

    // 0) segment offsets (GEMM1 epilogue needs g_sizes)
    hist_kernel<<<1, 256>>>(batch);

    // 1) conversions
    conv_split_kernel<<<4096, 256>>>(x, ah_p, al_p, (long)M_ROWS * KDIM / 4);
    conv_w_kernel<<<1024, 256>>>(w_qkv, w_out);

    // 2) qkv = x @ w_qkvT (2-term) + fused LN/scale epilogue
    mgemm_kernel<0><<<dim3(QKV3 / 128, M_ROWS / 128), 256, MG_SMEM>>>(
        ah_p, al_p, b1h_p, qkv_p, nullptr, batch, ln1w, ln1b, ln2w, ln2b);

    // 3) ktv per (b,h,g)
    ktv_kernel<<<B_SZ * HEADS * NGRAPH, 256>>>();

    // 4) attn = qn @ ktv[seg] -> fp16 hi/lo
    apply_kernel<<<B_SZ * HEADS * NGRAPH, 256>>>();

    // 5) out = attn @ w_outT + b_out (2-term)
    mgemm_kernel<1><<<dim3(DIM / 128, M_ROWS / 128), 256, MG_SMEM>>>(
        ath_p, atl_p, b2h_p, out, b_out, nullptr, nullptr, nullptr, nullptr, nullptr);
}

// round 7
// speedup vs baseline: 3.5829x; 1.1116x over previous
#include <cuda_runtime.h>
#include <cuda_fp16.h>
#include <cstdint>

// ---------------- problem constants (fixed by setup_inputs) ----------------
#define B_SZ   2
#define N_TOK  32768
#define DIM    512
#define HEADS  8
#define DH     64
#define NGRAPH 32
#define QKV3   1536
#define M_ROWS (B_SZ * N_TOK)          // 65536
#define KDIM   512
#define TILEMAX 288                    // max token-tiles per batch

// ---------------- device scratch (static; no allocations allowed) ----------
__device__ float  g_qkv [(size_t)M_ROWS * QKV3];          // k,v fp32 (cols 512..1535)
__device__ __half g_a_hi[(size_t)M_ROWS * KDIM];
__device__ __half g_a_lo[(size_t)M_ROWS * KDIM];
__device__ __half g_b1_hi[QKV3 * KDIM];
__device__ __half g_b2_hi[DIM * KDIM];
__device__ __half g_q_hi[((size_t)M_ROWS + 128) * DIM];   // +128 slack rows
__device__ __half g_q_lo[((size_t)M_ROWS + 128) * DIM];
__device__ __half g_attn_hi[(size_t)M_ROWS * DIM];
__device__ __half g_attn_lo[(size_t)M_ROWS * DIM];
__device__ __half g_ktvT_hi[B_SZ * HEADS * NGRAPH * DH * DH];
__device__ __half g_ktvT_lo[B_SZ * HEADS * NGRAPH * DH * DH];
__device__ int    g_sizes[NGRAPH];
__device__ int    g_off [NGRAPH + 1];
__device__ int    g_tile_g[TILEMAX];
__device__ int    g_tile_tok0[TILEMAX];
__device__ int    g_tile_nval[TILEMAX];

// ---------------- helpers ---------------------------------------------------
__device__ __forceinline__ uint32_t smem_u32(const void* p) {
    uint32_t a;
    asm("{ .reg .u64 t; cvta.to.shared.u64 t, %1; cvt.u32.u64 %0, t; }"
        : "=r"(a) : "l"(p));
    return a;
}
__device__ __forceinline__ void mma16816(float* d, const uint32_t* a, const uint32_t* b) {
    asm volatile(
        "mma.sync.aligned.m16n8k16.row.col.f32.f16.f16.f32 "
        "{%0,%1,%2,%3}, {%4,%5,%6,%7}, {%8,%9}, {%0,%1,%2,%3};"
        : "+f"(d[0]), "+f"(d[1]), "+f"(d[2]), "+f"(d[3])
        : "r"(a[0]), "r"(a[1]), "r"(a[2]), "r"(a[3]), "r"(b[0]), "r"(b[1]));
}
#define LDMX4(r, addr) \
    asm volatile("ldmatrix.sync.aligned.m8n8.x4.shared.b16 {%0,%1,%2,%3}, [%4];" \
                 : "=r"((r)[0]), "=r"((r)[1]), "=r"((r)[2]), "=r"((r)[3]) : "r"(addr))
#define CPA16(s, gp) \
    asm volatile("cp.async.cg.shared.global [%0], [%1], 16;" :: "r"(s), "l"(gp))

// ---------------- hist + tile tables ----------------------------------------
__global__ void hist_kernel(const int* __restrict__ batch) {
    __shared__ int cnt[NGRAPH];
    int tid = threadIdx.x;
    if (tid < NGRAPH) cnt[tid] = 0;
    __syncthreads();
    for (int i = tid; i < N_TOK; i += 256) atomicAdd(&cnt[batch[i]], 1);
    __syncthreads();
    if (tid == 0) {
        int off = 0;
        for (int g = 0; g < NGRAPH; g++) {
            g_off[g] = off; g_sizes[g] = cnt[g]; off += cnt[g];
        }
        g_off[NGRAPH] = off;
        int t = 0;
        for (int g = 0; g < NGRAPH; g++) {
            int S = g_sizes[g];
            for (int i = 0; i < S; i += 128) {
                g_tile_g[t] = g;
                g_tile_tok0[t] = g_off[g] + i;
                g_tile_nval[t] = (S - i < 128) ? (S - i) : 128;
                t++;
            }
        }
        for (; t < TILEMAX; t++) g_tile_nval[t] = 0;
    }
}

__device__ __forceinline__ void split4(float4 v, ushort4& vh, ushort4& vl) {
    __half h0 = __float2half_rn(v.x), h1 = __float2half_rn(v.y);
    __half h2 = __float2half_rn(v.z), h3 = __float2half_rn(v.w);
    __half l0 = __float2half_rn(v.x - __half2float(h0));
    __half l1 = __float2half_rn(v.y - __half2float(h1));
    __half l2 = __float2half_rn(v.z - __half2float(h2));
    __half l3 = __float2half_rn(v.w - __half2float(h3));
    vh.x = __half_as_ushort(h0); vh.y = __half_as_ushort(h1);
    vh.z = __half_as_ushort(h2); vh.w = __half_as_ushort(h3);
    vl.x = __half_as_ushort(l0); vl.y = __half_as_ushort(l1);
    vl.z = __half_as_ushort(l2); vl.w = __half_as_ushort(l3);
}
__device__ __forceinline__ ushort4 round4(float4 v) {
    ushort4 r;
    r.x = __half_as_ushort(__float2half_rn(v.x));
    r.y = __half_as_ushort(__float2half_rn(v.y));
    r.z = __half_as_ushort(__float2half_rn(v.z));
    r.w = __half_as_ushort(__float2half_rn(v.w));
    return r;
}

// fp32 -> (fp16 hi, fp16 lo) split, x4
__global__ void conv_split_kernel(const float* __restrict__ src,
                                  __half* __restrict__ hi,
                                  __half* __restrict__ lo, long n4) {
    long i = (long)blockIdx.x * blockDim.x + threadIdx.x;
    long stride = (long)gridDim.x * blockDim.x;
    for (; i < n4; i += stride) {
        ushort4 vh, vl;
        split4(((const float4*)src)[i], vh, vl);
        ((ushort4*)hi)[i] = vh;
        ((ushort4*)lo)[i] = vl;
    }
}

// weights: fp16 rounding (hi only), one launch
__global__ void conv_w_kernel(const float* __restrict__ w1,
                              const float* __restrict__ w2) {
    const long n1 = (long)QKV3 * KDIM / 4;
    const long n2 = (long)DIM * KDIM / 4;
    long i = (long)blockIdx.x * blockDim.x + threadIdx.x;
    long stride = (long)gridDim.x * blockDim.x;
    for (; i < n1 + n2; i += stride) {
        if (i < n1) ((ushort4*)g_b1_hi)[i]      = round4(((const float4*)w1)[i]);
        else        ((ushort4*)g_b2_hi)[i - n1] = round4(((const float4*)w2)[i - n1]);
    }
}

// ---------------- mma.sync split-fp16 GEMM (2-term, ldmatrix) ---------------
// MODE 0: qkv = x @ w_qkvT; epilogue: q -> fp16 hi/lo, k/v -> LN -> fp32
// MODE 1: out = attn @ w_outT + bias
#define TEN_BYTES (128 * 144)
#define MG_SMEM (2 * 3 * TEN_BYTES) // 110592 -> 2 CTAs/SM

__device__ __forceinline__ void issue_slab(uint32_t sdst, const __half* g,
                                           int k0, int tid) {
#pragma unroll
    for (int t = 0; t < 4; t++) {
        int id  = tid + t * 256;
        int row = id >> 3, col = id & 7;
        CPA16(sdst + row * 144 + col * 16, g + (size_t)row * KDIM + k0 + col * 8);
    }
}

template <int MODE>
__global__ __launch_bounds__(256, 2)
void mgemm_kernel(const __half* __restrict__ Ah, const __half* __restrict__ Al,
                  const __half* __restrict__ Bh,
                  float* __restrict__ C, const float* __restrict__ bias,
                  const int* __restrict__ batch,
                  const float* __restrict__ ln1w, const float* __restrict__ ln1b,
                  const float* __restrict__ ln2w, const float* __restrict__ ln2b) {
    constexpr int NC = (MODE == 0) ? QKV3 : DIM;
    extern __shared__ __align__(16) char smem[];
    uint32_t sb = smem_u32(smem);
    int tid = threadIdx.x, wid = tid >> 5, lane = tid & 31;
    int warpM = (wid & 3) * 32;
    int warpN = (wid >> 2) * 64;
    int g = lane >> 2, c2 = lane & 3;

    // ldmatrix per-lane offsets (144B row stride)
    uint32_t aoff = (lane & 15) * 144 + (lane >> 4) * 16;
    uint32_t boff = ((lane & 7) + ((lane >> 4) << 3)) * 144 + ((lane >> 3) & 1) * 16;

    const __half* pAh = Ah + (size_t)blockIdx.y * 128 * KDIM;
    const __half* pAl = Al + (size_t)blockIdx.y * 128 * KDIM;
    const __half* pBh = Bh + (size_t)blockIdx.x * 128 * KDIM;

#define ST(s, t) (sb + ((s) * 3 + (t)) * TEN_BYTES)
#define ISSUE_STAGE(s, k0)                        \
    do {                                          \
        issue_slab(ST(s, 0), pAh, (k0), tid);     \
        issue_slab(ST(s, 1), pAl, (k0), tid);     \
        issue_slab(ST(s, 2), pBh, (k0), tid);     \
        asm volatile("cp.async.commit_group;");   \
    } while (0)

    ISSUE_STAGE(0, 0);
    ISSUE_STAGE(1, 64);

    float acc[2][8][4];
#pragma unroll
    for (int i = 0; i < 2; i++)
#pragma unroll
        for (int j = 0; j < 8; j++)
#pragma unroll
            for (int k = 0; k < 4; k++) acc[i][j][k] = 0.0f;

    for (int it = 0; it < 8; it++) {
        int s = it & 1;
        if (it < 7) asm volatile("cp.async.wait_group 1;");
        else        asm volatile("cp.async.wait_group 0;");
        __syncthreads();
        uint32_t aA0 = ST(s, 0) + warpM * 144 + aoff;
        uint32_t aL0 = ST(s, 1) + warpM * 144 + aoff;
        uint32_t aB0 = ST(s, 2) + warpN * 144 + boff;
#pragma unroll
        for (int kk = 0; kk < 4; kk++) {
            int ko = kk * 32;
            uint32_t ah[2][4], al[2][4], bf[4][4];
            LDMX4(ah[0], aA0 + ko); LDMX4(ah[1], aA0 + 16 * 144 + ko);
            LDMX4(al[0], aL0 + ko); LDMX4(al[1], aL0 + 16 * 144 + ko);
#pragma unroll
            for (int p = 0; p < 4; p++) LDMX4(bf[p], aB0 + p * 16 * 144 + ko);
#pragma unroll
            for (int mt = 0; mt < 2; mt++)
#pragma unroll
                for (int nt = 0; nt < 8; nt++) {
                    const uint32_t* b = &bf[nt >> 1][(nt & 1) * 2];
                    mma16816(acc[mt][nt], ah[mt], b);
                    mma16816(acc[mt][nt], al[mt], b);
                }
        }
        __syncthreads();
        if (it + 2 < 8) ISSUE_STAGE(s, (it + 2) * 64);
    }

    // ---------------- epilogue ----------------
    if (MODE == 1) {
#pragma unroll
        for (int mt = 0; mt < 2; mt++) {
            size_t m0 = (size_t)blockIdx.y * 128 + warpM + mt * 16 + g;
#pragma unroll
            for (int nt = 0; nt < 8; nt++) {
                int nc = blockIdx.x * 128 + warpN + nt * 8 + c2 * 2;
                float b0 = bias[nc], b1 = bias[nc + 1];
                *(float2*)(C + m0 * NC + nc) =
                    make_float2(acc[mt][nt][0] + b0, acc[mt][nt][1] + b1);
                *(float2*)(C + (m0 + 8) * NC + nc) =
                    make_float2(acc[mt][nt][2] + b0, acc[mt][nt][3] + b1);
            }
        }
    } else {
        int mode = blockIdx.x >> 2;          // 0 q, 1 k, 2 v
        const float* lw = (mode == 1) ? ln1w : ln2w;
        const float* lb = (mode == 1) ? ln1b : ln2b;
#pragma unroll
        for (int mt = 0; mt < 2; mt++) {
#pragma unroll
            for (int hf = 0; hf < 2; hf++) {
                size_t m = (size_t)blockIdx.y * 128 + warpM + mt * 16 + g + hf * 8;
                float v[16];
#pragma unroll
                for (int nt = 0; nt < 8; nt++) {
                    v[nt * 2]     = acc[mt][nt][hf * 2];
                    v[nt * 2 + 1] = acc[mt][nt][hf * 2 + 1];
                }
                if (mode == 0) {
                    // q: scale, split to fp16 hi/lo
                    int n = (int)(m & (N_TOK - 1));
                    float sc = 1.0f / (float)g_sizes[batch[n]];
                    size_t base = m * DIM + blockIdx.x * 128 + warpN + c2 * 2;
#pragma unroll
                    for (int nt = 0; nt < 8; nt++) {
                        float f0 = v[nt * 2] * sc, f1 = v[nt * 2 + 1] * sc;
                        __half h0 = __float2half_rn(f0), h1 = __float2half_rn(f1);
                        __half l0 = __float2half_rn(f0 - __half2float(h0));
                        __half l1 = __float2half_rn(f1 - __half2float(h1));
                        ushort2 uh = make_ushort2(__half_as_ushort(h0), __half_as_ushort(h1));
                        ushort2 ul = make_ushort2(__half_as_ushort(l0), __half_as_ushort(l1));
                        *(ushort2*)((unsigned short*)g_q_hi + base + nt * 8) = uh;
                        *(ushort2*)((unsigned short*)g_q_lo + base + nt * 8) = ul;
                    }
                } else {
                    float s = 0.f, s2 = 0.f;
#pragma unroll
                    for (int k = 0; k < 16; k++) { s += v[k]; s2 += v[k] * v[k]; }
                    s  += __shfl_xor_sync(0xffffffffu, s, 1);
                    s  += __shfl_xor_sync(0xffffffffu, s, 2);
                    s2 += __shfl_xor_sync(0xffffffffu, s2, 1);
                    s2 += __shfl_xor_sync(0xffffffffu, s2, 2);
                    float mu = s * (1.0f / 64.0f);
                    float var = s2 * (1.0f / 64.0f) - mu * mu;
                    float rs = rsqrtf(var + 1e-6f);
                    float* cp = C + m * NC + blockIdx.x * 128 + warpN;
#pragma unroll
                    for (int nt = 0; nt < 8; nt++) {
                        int cl = nt * 8 + c2 * 2;     // head-local col
                        float f0 = (v[nt * 2]     - mu) * rs * lw[cl]     + lb[cl];
                        float f1 = (v[nt * 2 + 1] - mu) * rs * lw[cl + 1] + lb[cl + 1];
                        *(float2*)(cp + nt * 8 + c2 * 2) = make_float2(f0, f1);
                    }
                }
            }
        }
    }
#undef ST
#undef ISSUE_STAGE
}

// ---------------- ktv[b,h,g] = K_segT @ V_seg -> fp16 hi/lo TRANSPOSED -----
__global__ __launch_bounds__(256)
void ktv_kernel() {
    int g = blockIdx.x & 31;
    int h = (blockIdx.x >> 5) & 7;
    int b = blockIdx.x >> 8;
    int s0 = g_off[g], s1 = g_off[g + 1];

    __shared__ __align__(16) float sk[32][64];
    __shared__ __align__(16) float sv[32][64];

    int tid = threadIdx.x;
    int ti = tid >> 3;
    int jb = (tid & 7) * 8;
    int i0 = (tid >> 4) * 4;
    int j0 = (tid & 15) * 4;

    float acc[4][4];
#pragma unroll
    for (int i = 0; i < 4; i++)
#pragma unroll
        for (int j = 0; j < 4; j++) acc[i][j] = 0.0f;

    for (int t0 = s0; t0 < s1; t0 += 32) {
        int n = t0 + ti;
        if (n < s1) {
            const float* row = g_qkv + ((size_t)b * N_TOK + n) * QKV3 + 512 + h * DH + jb;
            *(float4*)&sk[ti][jb]     = *(const float4*)(row);
            *(float4*)&sk[ti][jb + 4] = *(const float4*)(row + 4);
            *(float4*)&sv[ti][jb]     = *(const float4*)(row + 512);
            *(float4*)&sv[ti][jb + 4] = *(const float4*)(row + 516);
        } else {
            float4 z = make_float4(0.f, 0.f, 0.f, 0.f);
            *(float4*)&sk[ti][jb] = z; *(float4*)&sk[ti][jb + 4] = z;
            *(float4*)&sv[ti][jb] = z; *(float4*)&sv[ti][jb + 4] = z;
        }
        __syncthreads();
#pragma unroll
        for (int t = 0; t < 32; t++) {
            float4 ka = *(float4*)&sk[t][i0];
            float4 vb = *(float4*)&sv[t][j0];
            acc[0][0] += ka.x * vb.x; acc[0][1] += ka.x * vb.y;
            acc[0][2] += ka.x * vb.z; acc[0][3] += ka.x * vb.w;
            acc[1][0] += ka.y * vb.x; acc[1][1] += ka.y * vb.y;
            acc[1][2] += ka.y * vb.z; acc[1][3] += ka.y * vb.w;
            acc[2][0] += ka.z * vb.x; acc[2][1] += ka.z * vb.y;
            acc[2][2] += ka.z * vb.z; acc[2][3] += ka.z * vb.w;
            acc[3][0] += ka.w * vb.x; acc[3][1] += ka.w * vb.y;
            acc[3][2] += ka.w * vb.z; acc[3][3] += ka.w * vb.w;
        }
        __syncthreads();
    }

    // write ktvT[e][d] = acc at (d=i0+i, e=j0+j), fp16 hi/lo
    size_t base = (size_t)blockIdx.x * DH * DH;
#pragma unroll
    for (int i = 0; i < 4; i++)
#pragma unroll
        for (int j = 0; j < 4; j++) {
            float f = acc[i][j];
            __half hb = __float2half_rn(f);
            __half lb = __float2half_rn(f - __half2float(hb));
            size_t o = base + (size_t)(j0 + j) * DH + (i0 + i);
            g_ktvT_hi[o] = hb;
            g_ktvT_lo[o] = lb;
        }
}

// ---------------- attn tile = q_tile @ ktvT (tensor, 3-term) ----------------
// grid (8 h, 288 tiles, 2 b); block 256 = 8 warps (4M x 2N), tile 128x64, K=64
#define AP_QSLAB (128 * 144)
#define AP_TSLAB (64 * 144)
#define AP_SMEM  (2 * AP_QSLAB + 2 * AP_TSLAB)   // 55296

__global__ __launch_bounds__(256, 2)
void applymma_kernel() {
    int h = blockIdx.x, ti = blockIdx.y, b = blockIdx.z;
    int nval = g_tile_nval[ti];
    if (nval == 0) return;
    int gseg = g_tile_g[ti];
    int tok0 = g_tile_tok0[ti];

    extern __shared__ __align__(16) char smem[];
    uint32_t sb = smem_u32(smem);
    uint32_t sQh = sb, sQl = sb + AP_QSLAB;
    uint32_t sTh = sb + 2 * AP_QSLAB, sTl = sTh + AP_TSLAB;

    int tid = threadIdx.x, wid = tid >> 5, lane = tid & 31;
    int warpM = (wid & 3) * 32;
    int warpN = (wid >> 2) * 32;
    int g = lane >> 2, c2 = lane & 3;

    // loads: Q slab 128 rows x 8 chunks (1024 cp.async), T slab 64 x 8 (512)
    {
        size_t qrow0 = (size_t)b * N_TOK + tok0;
#pragma unroll
        for (int t = 0; t < 4; t++) {
            int id = tid + t * 256;          // 0..1023
            int row = id >> 3, ch = id & 7;
            size_t go = (qrow0 + row) * DIM + h * DH + ch * 8;
            CPA16(sQh + row * 144 + ch * 16, (const __half*)g_q_hi + go);
            CPA16(sQl + row * 144 + ch * 16, (const __half*)g_q_lo + go);
        }
        size_t kbase = ((size_t)((b * HEADS + h) * NGRAPH + gseg)) * DH * DH;
#pragma unroll
        for (int t = 0; t < 2; t++) {
            int id = tid + t * 256;          // 0..511
            int row = id >> 3, ch = id & 7;
            size_t ko = kbase + (size_t)row * DH + ch * 8;
            CPA16(sTh + row * 144 + ch * 16, (const __half*)g_ktvT_hi + ko);
            CPA16(sTl + row * 144 + ch * 16, (const __half*)g_ktvT_lo + ko);
        }
        asm volatile("cp.async.commit_group;");
        asm volatile("cp.async.wait_group 0;");
        __syncthreads();
    }

    uint32_t aoff = (lane & 15) * 144 + (lane >> 4) * 16;
    uint32_t boff = ((lane & 7) + ((lane >> 4) << 3)) * 144 + ((lane >> 3) & 1) * 16;

    float acc[2][4][4];
#pragma unroll
    for (int i = 0; i < 2; i++)
#pragma unroll
        for (int j = 0; j < 4; j++)
#pragma unroll
            for (int k = 0; k < 4; k++) acc[i][j][k] = 0.0f;

    uint32_t aQh = sQh + warpM * 144 + aoff;
    uint32_t aQl = sQl + warpM * 144 + aoff;
    uint32_t aTh = sTh + warpN * 144 + boff;
    uint32_t aTl = sTl + warpN * 144 + boff;

#pragma unroll
    for (int kk = 0; kk < 4; kk++) {
        int ko = kk * 32;
        uint32_t qh[2][4], ql[2][4], bh[2][4], bl[2][4];
        LDMX4(qh[0], aQh + ko); LDMX4(qh[1], aQh + 16 * 144 + ko);
        LDMX4(ql[0], aQl + ko); LDMX4(ql[1], aQl + 16 * 144 + ko);
        LDMX4(bh[0], aTh + ko); LDMX4(bh[1], aTh + 16 * 144 + ko);
        LDMX4(bl[0], aTl + ko); LDMX4(bl[1], aTl + 16 * 144 + ko);
#pragma unroll
        for (int mt = 0; mt < 2; mt++)
#pragma unroll
            for (int nt = 0; nt < 4; nt++) {
                const uint32_t* bph = &bh[nt >> 1][(nt & 1) * 2];
                const uint32_t* bpl = &bl[nt >> 1][(nt & 1) * 2];
                mma16816(acc[mt][nt], qh[mt], bph);
                mma16816(acc[mt][nt], ql[mt], bph);
                mma16816(acc[mt][nt], qh[mt], bpl);
            }
    }

    // masked epilogue -> attn hi/lo
#pragma unroll
    for (int mt = 0; mt < 2; mt++) {
#pragma unroll
        for (int hf = 0; hf < 2; hf++) {
            int r = warpM + mt * 16 + g + hf * 8;
            if (r < nval) {
                size_t base = ((size_t)b * N_TOK + tok0 + r) * DIM + h * DH + warpN + c2 * 2;
#pragma unroll
                for (int nt = 0; nt < 4; nt++) {
                    float f0 = acc[mt][nt][hf * 2], f1 = acc[mt][nt][hf * 2 + 1];
                    __half h0 = __float2half_rn(f0), h1 = __float2half_rn(f1);
                    __half l0 = __float2half_rn(f0 - __half2float(h0));
                    __half l1 = __float2half_rn(f1 - __half2float(h1));
                    ushort2 uh = make_ushort2(__half_as_ushort(h0), __half_as_ushort(h1));
                    ushort2 ul = make_ushort2(__half_as_ushort(l0), __half_as_ushort(l1));
                    *(ushort2*)((unsigned short*)g_attn_hi + base + nt * 8) = uh;
                    *(ushort2*)((unsigned short*)g_attn_lo + base + nt * 8) = ul;
                }
            }
        }
    }
}

// ---------------- launch ----------------------------------------------------
extern "C" void kernel_launch(void* const* d_in, const int* in_sizes, int n_in,
                              void* d_out, int out_size) {
    const float* x     = (const float*)d_in[0];
    const float* w_qkv = (const float*)d_in[1];
    const float* ln1w  = (const float*)d_in[2];
    const float* ln1b  = (const float*)d_in[3];
    const float* ln2w  = (const float*)d_in[4];
    const float* ln2b  = (const float*)d_in[5];
    const float* w_out = (const float*)d_in[6];
    const float* b_out = (const float*)d_in[7];
    const int*   batch = (const int*)d_in[8];
    float* out = (float*)d_out;

    float* qkv_p;
    __half *ah_p, *al_p, *b1h_p, *b2h_p, *ath_p, *atl_p;
    cudaGetSymbolAddress((void**)&qkv_p, g_qkv);
    cudaGetSymbolAddress((void**)&ah_p,  g_a_hi);
    cudaGetSymbolAddress((void**)&al_p,  g_a_lo);
    cudaGetSymbolAddress((void**)&b1h_p, g_b1_hi);
    cudaGetSymbolAddress((void**)&b2h_p, g_b2_hi);
    cudaGetSymbolAddress((void**)&ath_p, g_attn_hi);
    cudaGetSymbolAddress((void**)&atl_p, g_attn_lo);

    cudaFuncSetAttribute(mgemm_kernel<0>, cudaFuncAttributeMaxDynamicSharedMemorySize, MG_SMEM);
    cudaFuncSetAttribute(mgemm_kernel<1>, cudaFuncAttributeMaxDynamicSharedMemorySize, MG_SMEM);
    cudaFuncSetAttribute(applymma_kernel, cudaFuncAttributeMaxDynamicSharedMemorySize, AP_SMEM);

    // 0) segment offsets + tile tables
    hist_kernel<<<1, 256>>>(batch);

    // 1) conversions
    conv_split_kernel<<<4096, 256>>>(x, ah_p, al_p, (long)M_ROWS * KDIM / 4);
    conv_w_kernel<<<1024, 256>>>(w_qkv, w_out);

    // 2) qkv GEMM (2-term, ldmatrix) + fused epilogue (q->fp16, k/v->LN fp32)
    mgemm_kernel<0><<<dim3(QKV3 / 128, M_ROWS / 128), 256, MG_SMEM>>>(
        ah_p, al_p, b1h_p, qkv_p, nullptr, batch, ln1w, ln1b, ln2w, ln2b);

    // 3) ktv per (b,h,g) -> fp16 hi/lo transposed
    ktv_kernel<<<B_SZ * HEADS * NGRAPH, 256>>>();

    // 4) attn = qn @ ktv (tensor, masked ragged tiles)
    applymma_kernel<<<dim3(HEADS, TILEMAX, B_SZ), 256, AP_SMEM>>>();

    // 5) out = attn @ w_outT + b_out (2-term, ldmatrix)
    mgemm_kernel<1><<<dim3(DIM / 128, M_ROWS / 128), 256, MG_SMEM>>>(
        ath_p, atl_p, b2h_p, out, b_out, nullptr, nullptr, nullptr, nullptr, nullptr);
}

// round 9
// speedup vs baseline: 3.8406x; 1.0719x over previous
#include <cuda_runtime.h>
#include <cuda_fp16.h>
#include <cstdint>

// ---------------- problem constants (fixed by setup_inputs) ----------------
#define B_SZ   2
#define N_TOK  32768
#define DIM    512
#define HEADS  8
#define DH     64
#define NGRAPH 32
#define QKV3   1536
#define M_ROWS (B_SZ * N_TOK)          // 65536
#define KDIM   512
#define TILEMAX 288                    // max token-tiles per batch

// ---------------- device scratch (static; no allocations allowed) ----------
__device__ __half g_a_hi[(size_t)M_ROWS * KDIM];
__device__ __half g_a_lo[(size_t)M_ROWS * KDIM];
__device__ __half g_b1_hi[QKV3 * KDIM];
__device__ __half g_b2_hi[DIM * KDIM];
__device__ __half g_q_hi[((size_t)M_ROWS + 128) * DIM];   // +128 slack rows
__device__ __half g_q_lo[((size_t)M_ROWS + 128) * DIM];
__device__ __half g_k_hi[(size_t)M_ROWS * DIM];
__device__ __half g_k_lo[(size_t)M_ROWS * DIM];
__device__ __half g_v_hi[(size_t)M_ROWS * DIM];
__device__ __half g_v_lo[(size_t)M_ROWS * DIM];
__device__ __half g_attn_hi[(size_t)M_ROWS * DIM];
__device__ __half g_attn_lo[(size_t)M_ROWS * DIM];
__device__ __half g_ktvT_hi[B_SZ * HEADS * NGRAPH * DH * DH];
__device__ __half g_ktvT_lo[B_SZ * HEADS * NGRAPH * DH * DH];
__device__ int    g_sizes[NGRAPH];
__device__ int    g_off [NGRAPH + 1];
__device__ int    g_tile_g[TILEMAX];
__device__ int    g_tile_tok0[TILEMAX];
__device__ int    g_tile_nval[TILEMAX];

// ---------------- helpers ---------------------------------------------------
__device__ __forceinline__ uint32_t smem_u32(const void* p) {
    uint32_t a;
    asm("{ .reg .u64 t; cvta.to.shared.u64 t, %1; cvt.u32.u64 %0, t; }"
        : "=r"(a) : "l"(p));
    return a;
}
__device__ __forceinline__ void mma16816(float* d, const uint32_t* a, const uint32_t* b) {
    asm volatile(
        "mma.sync.aligned.m16n8k16.row.col.f32.f16.f16.f32 "
        "{%0,%1,%2,%3}, {%4,%5,%6,%7}, {%8,%9}, {%0,%1,%2,%3};"
        : "+f"(d[0]), "+f"(d[1]), "+f"(d[2]), "+f"(d[3])
        : "r"(a[0]), "r"(a[1]), "r"(a[2]), "r"(a[3]), "r"(b[0]), "r"(b[1]));
}
#define LDMX4(r, addr) \
    asm volatile("ldmatrix.sync.aligned.m8n8.x4.shared.b16 {%0,%1,%2,%3}, [%4];" \
                 : "=r"((r)[0]), "=r"((r)[1]), "=r"((r)[2]), "=r"((r)[3]) : "r"(addr))
#define LDMX4T(r, addr) \
    asm volatile("ldmatrix.sync.aligned.m8n8.x4.trans.shared.b16 {%0,%1,%2,%3}, [%4];" \
                 : "=r"((r)[0]), "=r"((r)[1]), "=r"((r)[2]), "=r"((r)[3]) : "r"(addr))
#define CPA16(s, gp) \
    asm volatile("cp.async.cg.shared.global [%0], [%1], 16;" :: "r"(s), "l"(gp))

// ---------------- hist + tile tables ----------------------------------------
__global__ void hist_kernel(const int* __restrict__ batch) {
    __shared__ int cnt[NGRAPH];
    int tid = threadIdx.x;
    if (tid < NGRAPH) cnt[tid] = 0;
    __syncthreads();
    for (int i = tid; i < N_TOK; i += 256) atomicAdd(&cnt[batch[i]], 1);
    __syncthreads();
    if (tid == 0) {
        int off = 0;
        for (int g = 0; g < NGRAPH; g++) {
            g_off[g] = off; g_sizes[g] = cnt[g]; off += cnt[g];
        }
        g_off[NGRAPH] = off;
        int t = 0;
        for (int g = 0; g < NGRAPH; g++) {
            int S = g_sizes[g];
            for (int i = 0; i < S; i += 128) {
                g_tile_g[t] = g;
                g_tile_tok0[t] = g_off[g] + i;
                g_tile_nval[t] = (S - i < 128) ? (S - i) : 128;
                t++;
            }
        }
        for (; t < TILEMAX; t++) g_tile_nval[t] = 0;
    }
}

__device__ __forceinline__ void split4(float4 v, ushort4& vh, ushort4& vl) {
    __half h0 = __float2half_rn(v.x), h1 = __float2half_rn(v.y);
    __half h2 = __float2half_rn(v.z), h3 = __float2half_rn(v.w);
    __half l0 = __float2half_rn(v.x - __half2float(h0));
    __half l1 = __float2half_rn(v.y - __half2float(h1));
    __half l2 = __float2half_rn(v.z - __half2float(h2));
    __half l3 = __float2half_rn(v.w - __half2float(h3));
    vh.x = __half_as_ushort(h0); vh.y = __half_as_ushort(h1);
    vh.z = __half_as_ushort(h2); vh.w = __half_as_ushort(h3);
    vl.x = __half_as_ushort(l0); vl.y = __half_as_ushort(l1);
    vl.z = __half_as_ushort(l2); vl.w = __half_as_ushort(l3);
}
__device__ __forceinline__ void split2(float f0, float f1, ushort2& uh, ushort2& ul) {
    __half h0 = __float2half_rn(f0), h1 = __float2half_rn(f1);
    __half l0 = __float2half_rn(f0 - __half2float(h0));
    __half l1 = __float2half_rn(f1 - __half2float(h1));
    uh = make_ushort2(__half_as_ushort(h0), __half_as_ushort(h1));
    ul = make_ushort2(__half_as_ushort(l0), __half_as_ushort(l1));
}
__device__ __forceinline__ ushort4 round4(float4 v) {
    ushort4 r;
    r.x = __half_as_ushort(__float2half_rn(v.x));
    r.y = __half_as_ushort(__float2half_rn(v.y));
    r.z = __half_as_ushort(__float2half_rn(v.z));
    r.w = __half_as_ushort(__float2half_rn(v.w));
    return r;
}

// fp32 -> (fp16 hi, fp16 lo) split, x4
__global__ void conv_split_kernel(const float* __restrict__ src,
                                  __half* __restrict__ hi,
                                  __half* __restrict__ lo, long n4) {
    long i = (long)blockIdx.x * blockDim.x + threadIdx.x;
    long stride = (long)gridDim.x * blockDim.x;
    for (; i < n4; i += stride) {
        ushort4 vh, vl;
        split4(((const float4*)src)[i], vh, vl);
        ((ushort4*)hi)[i] = vh;
        ((ushort4*)lo)[i] = vl;
    }
}

// weights: fp16 rounding (hi only), one launch
__global__ void conv_w_kernel(const float* __restrict__ w1,
                              const float* __restrict__ w2) {
    const long n1 = (long)QKV3 * KDIM / 4;
    const long n2 = (long)DIM * KDIM / 4;
    long i = (long)blockIdx.x * blockDim.x + threadIdx.x;
    long stride = (long)gridDim.x * blockDim.x;
    for (; i < n1 + n2; i += stride) {
        if (i < n1) ((ushort4*)g_b1_hi)[i]      = round4(((const float4*)w1)[i]);
        else        ((ushort4*)g_b2_hi)[i - n1] = round4(((const float4*)w2)[i - n1]);
    }
}

// ---------------- mma.sync split-fp16 GEMM (2-term, ldmatrix) ---------------
// MODE 0: qkv = x @ w_qkvT; epilogue: q/k/v -> fp16 hi/lo (k,v LayerNormed)
// MODE 1: out = attn @ w_outT + bias
#define TEN_BYTES (128 * 144)
#define MG_SMEM (2 * 3 * TEN_BYTES) // 110592 -> 2 CTAs/SM

__device__ __forceinline__ void issue_slab(uint32_t sdst, const __half* g,
                                           int k0, int tid) {
#pragma unroll
    for (int t = 0; t < 4; t++) {
        int id  = tid + t * 256;
        int row = id >> 3, col = id & 7;
        CPA16(sdst + row * 144 + col * 16, g + (size_t)row * KDIM + k0 + col * 8);
    }
}

template <int MODE>
__global__ __launch_bounds__(256, 2)
void mgemm_kernel(const __half* __restrict__ Ah, const __half* __restrict__ Al,
                  const __half* __restrict__ Bh,
                  float* __restrict__ C, const float* __restrict__ bias,
                  const int* __restrict__ batch,
                  const float* __restrict__ ln1w, const float* __restrict__ ln1b,
                  const float* __restrict__ ln2w, const float* __restrict__ ln2b) {
    extern __shared__ __align__(16) char smem[];
    uint32_t sb = smem_u32(smem);
    int tid = threadIdx.x, wid = tid >> 5, lane = tid & 31;
    int warpM = (wid & 3) * 32;
    int warpN = (wid >> 2) * 64;
    int g = lane >> 2, c2 = lane & 3;

    // ldmatrix per-lane offsets (144B row stride)
    uint32_t aoff = (lane & 15) * 144 + (lane >> 4) * 16;
    uint32_t boff = ((lane & 7) + ((lane >> 4) << 3)) * 144 + ((lane >> 3) & 1) * 16;

    const __half* pAh = Ah + (size_t)blockIdx.y * 128 * KDIM;
    const __half* pAl = Al + (size_t)blockIdx.y * 128 * KDIM;
    const __half* pBh = Bh + (size_t)blockIdx.x * 128 * KDIM;

#define ST(s, t) (sb + ((s) * 3 + (t)) * TEN_BYTES)
#define ISSUE_STAGE(s, k0)                        \
    do {                                          \
        issue_slab(ST(s, 0), pAh, (k0), tid);     \
        issue_slab(ST(s, 1), pAl, (k0), tid);     \
        issue_slab(ST(s, 2), pBh, (k0), tid);     \
        asm volatile("cp.async.commit_group;");   \
    } while (0)

    ISSUE_STAGE(0, 0);
    ISSUE_STAGE(1, 64);

    float acc[2][8][4];
#pragma unroll
    for (int i = 0; i < 2; i++)
#pragma unroll
        for (int j = 0; j < 8; j++)
#pragma unroll
            for (int k = 0; k < 4; k++) acc[i][j][k] = 0.0f;

    for (int it = 0; it < 8; it++) {
        int s = it & 1;
        if (it < 7) asm volatile("cp.async.wait_group 1;");
        else        asm volatile("cp.async.wait_group 0;");
        __syncthreads();
        uint32_t aA0 = ST(s, 0) + warpM * 144 + aoff;
        uint32_t aL0 = ST(s, 1) + warpM * 144 + aoff;
        uint32_t aB0 = ST(s, 2) + warpN * 144 + boff;
#pragma unroll
        for (int kk = 0; kk < 4; kk++) {
            int ko = kk * 32;
            uint32_t ah[2][4], al[2][4], bf[4][4];
            LDMX4(ah[0], aA0 + ko); LDMX4(ah[1], aA0 + 16 * 144 + ko);
            LDMX4(al[0], aL0 + ko); LDMX4(al[1], aL0 + 16 * 144 + ko);
#pragma unroll
            for (int p = 0; p < 4; p++) LDMX4(bf[p], aB0 + p * 16 * 144 + ko);
            // term-major: 16 independent HMMAs between dependent pairs
#pragma unroll
            for (int mt = 0; mt < 2; mt++)
#pragma unroll
                for (int nt = 0; nt < 8; nt++)
                    mma16816(acc[mt][nt], ah[mt], &bf[nt >> 1][(nt & 1) * 2]);
#pragma unroll
            for (int mt = 0; mt < 2; mt++)
#pragma unroll
                for (int nt = 0; nt < 8; nt++)
                    mma16816(acc[mt][nt], al[mt], &bf[nt >> 1][(nt & 1) * 2]);
        }
        __syncthreads();
        if (it + 2 < 8) ISSUE_STAGE(s, (it + 2) * 64);
    }

    // ---------------- epilogue ----------------
    if (MODE == 1) {
#pragma unroll
        for (int mt = 0; mt < 2; mt++) {
            size_t m0 = (size_t)blockIdx.y * 128 + warpM + mt * 16 + g;
#pragma unroll
            for (int nt = 0; nt < 8; nt++) {
                int nc = blockIdx.x * 128 + warpN + nt * 8 + c2 * 2;
                float b0 = bias[nc], b1 = bias[nc + 1];
                *(float2*)(C + m0 * DIM + nc) =
                    make_float2(acc[mt][nt][0] + b0, acc[mt][nt][1] + b1);
                *(float2*)(C + (m0 + 8) * DIM + nc) =
                    make_float2(acc[mt][nt][2] + b0, acc[mt][nt][3] + b1);
            }
        }
    } else {
        // q: scale + split; k: LN(ln1) + split; v: LN(ln2) + split
        int mode = blockIdx.x >> 2;          // 0 q, 1 k, 2 v
        const float* lw = (mode == 1) ? ln1w : ln2w;
        const float* lb = (mode == 1) ? ln1b : ln2b;
        __half* dh = (mode == 0) ? g_q_hi : (mode == 1) ? g_k_hi : g_v_hi;
        __half* dl = (mode == 0) ? g_q_lo : (mode == 1) ? g_k_lo : g_v_lo;
        int colbase = blockIdx.x * 128 - mode * 512 + warpN;   // 0..511 in buffer
#pragma unroll
        for (int mt = 0; mt < 2; mt++) {
#pragma unroll
            for (int hf = 0; hf < 2; hf++) {
                size_t m = (size_t)blockIdx.y * 128 + warpM + mt * 16 + g + hf * 8;
                float v[16];
#pragma unroll
                for (int nt = 0; nt < 8; nt++) {
                    v[nt * 2]     = acc[mt][nt][hf * 2];
                    v[nt * 2 + 1] = acc[mt][nt][hf * 2 + 1];
                }
                if (mode == 0) {
                    int n = (int)(m & (N_TOK - 1));
                    float sc = 1.0f / (float)g_sizes[batch[n]];
#pragma unroll
                    for (int k = 0; k < 16; k++) v[k] *= sc;
                } else {
                    float s = 0.f, s2 = 0.f;
#pragma unroll
                    for (int k = 0; k < 16; k++) { s += v[k]; s2 += v[k] * v[k]; }
                    s  += __shfl_xor_sync(0xffffffffu, s, 1);
                    s  += __shfl_xor_sync(0xffffffffu, s, 2);
                    s2 += __shfl_xor_sync(0xffffffffu, s2, 1);
                    s2 += __shfl_xor_sync(0xffffffffu, s2, 2);
                    float mu = s * (1.0f / 64.0f);
                    float var = s2 * (1.0f / 64.0f) - mu * mu;
                    float rs = rsqrtf(var + 1e-6f);
#pragma unroll
                    for (int nt = 0; nt < 8; nt++) {
                        int cl = ((warpN + nt * 8 + c2 * 2) & 63); // head-local
                        v[nt * 2]     = (v[nt * 2]     - mu) * rs * lw[cl]     + lb[cl];
                        v[nt * 2 + 1] = (v[nt * 2 + 1] - mu) * rs * lw[cl + 1] + lb[cl + 1];
                    }
                }
                size_t base = m * DIM + colbase + c2 * 2;
#pragma unroll
                for (int nt = 0; nt < 8; nt++) {
                    ushort2 uh, ul;
                    split2(v[nt * 2], v[nt * 2 + 1], uh, ul);
                    *(ushort2*)((unsigned short*)dh + base + nt * 8) = uh;
                    *(ushort2*)((unsigned short*)dl + base + nt * 8) = ul;
                }
            }
        }
    }
#undef ST
#undef ISSUE_STAGE
}

// ---------------- ktvT[b,h,g] = (V_seg)^T-contract (tensor, 3-term) ---------
// D[e][d] = sum_tok V[tok][e] * K[tok][d]; both operands via ldmatrix.trans.
// 128 threads = 4 warps; warp w covers e rows w*16..w*16+15, d cols 0..63.
#define KT_SLAB  (64 * 144)
#define KT_STAGE (4 * KT_SLAB)
#define KT_SMEM  (2 * KT_STAGE)      // 73728

__global__ __launch_bounds__(128, 2)
void ktvmma_kernel() {
    int gseg = blockIdx.x & 31;
    int h = (blockIdx.x >> 5) & 7;
    int b = blockIdx.x >> 8;
    int s0 = g_off[gseg], s1 = g_off[gseg + 1];
    int NCH = (s1 - s0 + 63) >> 6;
    if (NCH <= 0) NCH = 1;

    extern __shared__ __align__(16) char smem[];
    uint32_t sb = smem_u32(smem);
    int tid = threadIdx.x, wid = tid >> 5, lane = tid & 31;
    int lg = lane >> 2, c2 = lane & 3;

#define KT_ISSUE(st, c)                                                        \
    do {                                                                       \
        int t0 = s0 + (c) * 64;                                                \
        uint32_t base = sb + (st) * KT_STAGE;                                  \
        char* cbase = smem + (st) * KT_STAGE;                                  \
        _Pragma("unroll")                                                      \
        for (int i = 0; i < 4; i++) {                                          \
            int id = tid + i * 128;                                            \
            int row = id >> 3, ch = id & 7;                                    \
            int tok = t0 + row;                                                \
            uint32_t so = row * 144 + ch * 16;                                 \
            if (tok < s1) {                                                    \
                size_t go = ((size_t)b * N_TOK + tok) * DIM + h * DH + ch * 8; \
                CPA16(base + 0 * KT_SLAB + so, g_k_hi + go);                   \
                CPA16(base + 1 * KT_SLAB + so, g_k_lo + go);                   \
                CPA16(base + 2 * KT_SLAB + so, g_v_hi + go);                   \
                CPA16(base + 3 * KT_SLAB + so, g_v_lo + go);                   \
            } else {                                                           \
                uint4 z = make_uint4(0, 0, 0, 0);                              \
                *(uint4*)(cbase + 0 * KT_SLAB + so) = z;                       \
                *(uint4*)(cbase + 1 * KT_SLAB + so) = z;                       \
                *(uint4*)(cbase + 2 * KT_SLAB + so) = z;                       \
                *(uint4*)(cbase + 3 * KT_SLAB + so) = z;                       \
            }                                                                  \
        }                                                                      \
        asm volatile("cp.async.commit_group;");                                \
    } while (0)

    KT_ISSUE(0, 0);
    if (NCH > 1) KT_ISSUE(1, 1);

    // trans ldmatrix lane offsets (derived from S<->S^T identity)
    uint32_t aoffT = ((lane & 7) + (lane >> 4) * 8) * 144 + ((lane >> 3) & 1) * 16;
    uint32_t boffT = ((lane & 7) + ((lane >> 3) & 1) * 8) * 144 + (lane >> 4) * 16;

    float acc[8][4];
#pragma unroll
    for (int j = 0; j < 8; j++)
#pragma unroll
        for (int k = 0; k < 4; k++) acc[j][k] = 0.0f;

    for (int c = 0; c < NCH; c++) {
        int st = c & 1;
        if (c + 2 <= NCH) asm volatile("cp.async.wait_group 1;");
        else              asm volatile("cp.async.wait_group 0;");
        __syncthreads();
        uint32_t base = sb + st * KT_STAGE;
        uint32_t aKh = base + 0 * KT_SLAB + boffT;
        uint32_t aKl = base + 1 * KT_SLAB + boffT;
        uint32_t aVh = base + 2 * KT_SLAB + wid * 32 + aoffT;
        uint32_t aVl = base + 3 * KT_SLAB + wid * 32 + aoffT;
#pragma unroll
        for (int kk = 0; kk < 4; kk++) {
            int ko = kk * (16 * 144);
            uint32_t vh[4], vl[4], kh[4][4], kl[4][4];
            LDMX4T(vh, aVh + ko);
            LDMX4T(vl, aVl + ko);
#pragma unroll
            for (int nb = 0; nb < 4; nb++) {
                LDMX4T(kh[nb], aKh + nb * 32 + ko);
                LDMX4T(kl[nb], aKl + nb * 32 + ko);
            }
#pragma unroll
            for (int nt = 0; nt < 8; nt++)
                mma16816(acc[nt], vh, &kh[nt >> 1][(nt & 1) * 2]);
#pragma unroll
            for (int nt = 0; nt < 8; nt++)
                mma16816(acc[nt], vl, &kh[nt >> 1][(nt & 1) * 2]);
#pragma unroll
            for (int nt = 0; nt < 8; nt++)
                mma16816(acc[nt], vh, &kl[nt >> 1][(nt & 1) * 2]);
        }
        __syncthreads();
        if (c + 2 < NCH) KT_ISSUE(st, c + 2);
    }

    // epilogue: ktvT[e][d], e = wid*16 + lg (+8), d = nt*8 + c2*2
    size_t kb = (size_t)blockIdx.x * (DH * DH);
    int r0 = wid * 16 + lg;
#pragma unroll
    for (int nt = 0; nt < 8; nt++) {
        int cidx = nt * 8 + c2 * 2;
        ushort2 uh, ul;
        split2(acc[nt][0], acc[nt][1], uh, ul);
        *(ushort2*)((unsigned short*)g_ktvT_hi + kb + (size_t)r0 * DH + cidx) = uh;
        *(ushort2*)((unsigned short*)g_ktvT_lo + kb + (size_t)r0 * DH + cidx) = ul;
        split2(acc[nt][2], acc[nt][3], uh, ul);
        *(ushort2*)((unsigned short*)g_ktvT_hi + kb + (size_t)(r0 + 8) * DH + cidx) = uh;
        *(ushort2*)((unsigned short*)g_ktvT_lo + kb + (size_t)(r0 + 8) * DH + cidx) = ul;
    }
#undef KT_ISSUE
}

// ---------------- attn tile = q_tile @ ktvT (tensor, 3-term) ----------------
#define AP_QSLAB (128 * 144)
#define AP_TSLAB (64 * 144)
#define AP_SMEM  (2 * AP_QSLAB + 2 * AP_TSLAB)   // 55296

__global__ __launch_bounds__(256, 2)
void applymma_kernel() {
    int h = blockIdx.x, ti = blockIdx.y, b = blockIdx.z;
    int nval = g_tile_nval[ti];
    if (nval == 0) return;
    int gseg = g_tile_g[ti];
    int tok0 = g_tile_tok0[ti];

    extern __shared__ __align__(16) char smem[];
    uint32_t sb = smem_u32(smem);
    uint32_t sQh = sb, sQl = sb + AP_QSLAB;
    uint32_t sTh = sb + 2 * AP_QSLAB, sTl = sTh + AP_TSLAB;

    int tid = threadIdx.x, wid = tid >> 5, lane = tid & 31;
    int warpM = (wid & 3) * 32;
    int warpN = (wid >> 2) * 32;
    int g = lane >> 2, c2 = lane & 3;

    {
        size_t qrow0 = (size_t)b * N_TOK + tok0;
#pragma unroll
        for (int t = 0; t < 4; t++) {
            int id = tid + t * 256;          // 0..1023
            int row = id >> 3, ch = id & 7;
            size_t go = (qrow0 + row) * DIM + h * DH + ch * 8;
            CPA16(sQh + row * 144 + ch * 16, (const __half*)g_q_hi + go);
            CPA16(sQl + row * 144 + ch * 16, (const __half*)g_q_lo + go);
        }
        size_t kbase = ((size_t)((b * HEADS + h) * NGRAPH + gseg)) * DH * DH;
#pragma unroll
        for (int t = 0; t < 2; t++) {
            int id = tid + t * 256;          // 0..511
            int row = id >> 3, ch = id & 7;
            size_t ko = kbase + (size_t)row * DH + ch * 8;
            CPA16(sTh + row * 144 + ch * 16, (const __half*)g_ktvT_hi + ko);
            CPA16(sTl + row * 144 + ch * 16, (const __half*)g_ktvT_lo + ko);
        }
        asm volatile("cp.async.commit_group;");
        asm volatile("cp.async.wait_group 0;");
        __syncthreads();
    }

    uint32_t aoff = (lane & 15) * 144 + (lane >> 4) * 16;
    uint32_t boff = ((lane & 7) + ((lane >> 4) << 3)) * 144 + ((lane >> 3) & 1) * 16;

    float acc[2][4][4];
#pragma unroll
    for (int i = 0; i < 2; i++)
#pragma unroll
        for (int j = 0; j < 4; j++)
#pragma unroll
            for (int k = 0; k < 4; k++) acc[i][j][k] = 0.0f;

    uint32_t aQh = sQh + warpM * 144 + aoff;
    uint32_t aQl = sQl + warpM * 144 + aoff;
    uint32_t aTh = sTh + warpN * 144 + boff;
    uint32_t aTl = sTl + warpN * 144 + boff;

#pragma unroll
    for (int kk = 0; kk < 4; kk++) {
        int ko = kk * 32;
        uint32_t qh[2][4], ql[2][4], bh[2][4], bl[2][4];
        LDMX4(qh[0], aQh + ko); LDMX4(qh[1], aQh + 16 * 144 + ko);
        LDMX4(ql[0], aQl + ko); LDMX4(ql[1], aQl + 16 * 144 + ko);
        LDMX4(bh[0], aTh + ko); LDMX4(bh[1], aTh + 16 * 144 + ko);
        LDMX4(bl[0], aTl + ko); LDMX4(bl[1], aTl + 16 * 144 + ko);
#pragma unroll
        for (int mt = 0; mt < 2; mt++)
#pragma unroll
            for (int nt = 0; nt < 4; nt++)
                mma16816(acc[mt][nt], qh[mt], &bh[nt >> 1][(nt & 1) * 2]);
#pragma unroll
        for (int mt = 0; mt < 2; mt++)
#pragma unroll
            for (int nt = 0; nt < 4; nt++)
                mma16816(acc[mt][nt], ql[mt], &bh[nt >> 1][(nt & 1) * 2]);
#pragma unroll
        for (int mt = 0; mt < 2; mt++)
#pragma unroll
            for (int nt = 0; nt < 4; nt++)
                mma16816(acc[mt][nt], qh[mt], &bl[nt >> 1][(nt & 1) * 2]);
    }

    // masked epilogue -> attn hi/lo
#pragma unroll
    for (int mt = 0; mt < 2; mt++) {
#pragma unroll
        for (int hf = 0; hf < 2; hf++) {
            int r = warpM + mt * 16 + g + hf * 8;
            if (r < nval) {
                size_t base = ((size_t)b * N_TOK + tok0 + r) * DIM + h * DH + warpN + c2 * 2;
#pragma unroll
                for (int nt = 0; nt < 4; nt++) {
                    ushort2 uh, ul;
                    split2(acc[mt][nt][hf * 2], acc[mt][nt][hf * 2 + 1], uh, ul);
                    *(ushort2*)((unsigned short*)g_attn_hi + base + nt * 8) = uh;
                    *(ushort2*)((unsigned short*)g_attn_lo + base + nt * 8) = ul;
                }
            }
        }
    }
}

// ---------------- launch ----------------------------------------------------
extern "C" void kernel_launch(void* const* d_in, const int* in_sizes, int n_in,
                              void* d_out, int out_size) {
    const float* x     = (const float*)d_in[0];
    const float* w_qkv = (const float*)d_in[1];
    const float* ln1w  = (const float*)d_in[2];
    const float* ln1b  = (const float*)d_in[3];
    const float* ln2w  = (const float*)d_in[4];
    const float* ln2b  = (const float*)d_in[5];
    const float* w_out = (const float*)d_in[6];
    const float* b_out = (const float*)d_in[7];
    const int*   batch = (const int*)d_in[8];
    float* out = (float*)d_out;

    __half *ah_p, *al_p, *b1h_p, *b2h_p, *ath_p, *atl_p;
    cudaGetSymbolAddress((void**)&ah_p,  g_a_hi);
    cudaGetSymbolAddress((void**)&al_p,  g_a_lo);
    cudaGetSymbolAddress((void**)&b1h_p, g_b1_hi);
    cudaGetSymbolAddress((void**)&b2h_p, g_b2_hi);
    cudaGetSymbolAddress((void**)&ath_p, g_attn_hi);
    cudaGetSymbolAddress((void**)&atl_p, g_attn_lo);

    cudaFuncSetAttribute(mgemm_kernel<0>, cudaFuncAttributeMaxDynamicSharedMemorySize, MG_SMEM);
    cudaFuncSetAttribute(mgemm_kernel<1>, cudaFuncAttributeMaxDynamicSharedMemorySize, MG_SMEM);
    cudaFuncSetAttribute(ktvmma_kernel,   cudaFuncAttributeMaxDynamicSharedMemorySize, KT_SMEM);
    cudaFuncSetAttribute(applymma_kernel, cudaFuncAttributeMaxDynamicSharedMemorySize, AP_SMEM);

    // 0) segment offsets + tile tables
    hist_kernel<<<1, 256>>>(batch);

    // 1) conversions
    conv_split_kernel<<<4096, 256>>>(x, ah_p, al_p, (long)M_ROWS * KDIM / 4);
    conv_w_kernel<<<1024, 256>>>(w_qkv, w_out);

    // 2) qkv GEMM (2-term) + fused epilogue (q/k/v -> fp16 hi/lo, k/v LN'd)
    mgemm_kernel<0><<<dim3(QKV3 / 128, M_ROWS / 128), 256, MG_SMEM>>>(
        ah_p, al_p, b1h_p, nullptr, nullptr, batch, ln1w, ln1b, ln2w, ln2b);

    // 3) ktvT per (b,h,g) (tensor, 3-term, ldmatrix.trans)
    ktvmma_kernel<<<B_SZ * HEADS * NGRAPH, 128, KT_SMEM>>>();

    // 4) attn = qn @ ktv (tensor, masked ragged tiles)
    applymma_kernel<<<dim3(HEADS, TILEMAX, B_SZ), 256, AP_SMEM>>>();

    // 5) out = attn @ w_outT + b_out (2-term)
    mgemm_kernel<1><<<dim3(DIM / 128, M_ROWS / 128), 256, MG_SMEM>>>(
        ath_p, atl_p, b2h_p, out, b_out, nullptr, nullptr, nullptr, nullptr, nullptr);
}

// round 10
// speedup vs baseline: 4.8874x; 1.2726x over previous
#include <cuda_runtime.h>
#include <cuda_fp16.h>
#include <cstdint>

// ---------------- problem constants (fixed by setup_inputs) ----------------
#define B_SZ   2
#define N_TOK  32768
#define DIM    512
#define HEADS  8
#define DH     64
#define NGRAPH 32
#define QKV3   1536
#define M_ROWS (B_SZ * N_TOK)          // 65536
#define KDIM   512
#define TILEMAX 288                    // max token-tiles per batch

// ---------------- device scratch (static; no allocations allowed) ----------
__device__ __half g_a_hi[(size_t)M_ROWS * KDIM];
__device__ __half g_b1_hi[QKV3 * KDIM];
__device__ __half g_b2_hi[DIM * KDIM];
__device__ __half g_q_hi[((size_t)M_ROWS + 128) * DIM];   // +128 slack rows
__device__ __half g_q_lo[((size_t)M_ROWS + 128) * DIM];
__device__ __half g_k_hi[(size_t)M_ROWS * DIM];
__device__ __half g_k_lo[(size_t)M_ROWS * DIM];
__device__ __half g_v_hi[(size_t)M_ROWS * DIM];
__device__ __half g_v_lo[(size_t)M_ROWS * DIM];
__device__ __half g_attn_hi[(size_t)M_ROWS * DIM];
__device__ __half g_attn_lo[(size_t)M_ROWS * DIM];
__device__ __half g_ktvT_hi[B_SZ * HEADS * NGRAPH * DH * DH];
__device__ __half g_ktvT_lo[B_SZ * HEADS * NGRAPH * DH * DH];
__device__ int    g_sizes[NGRAPH];
__device__ int    g_off [NGRAPH + 1];
__device__ int    g_tile_g[TILEMAX];
__device__ int    g_tile_tok0[TILEMAX];
__device__ int    g_tile_nval[TILEMAX];

// ---------------- helpers ---------------------------------------------------
__device__ __forceinline__ uint32_t smem_u32(const void* p) {
    uint32_t a;
    asm("{ .reg .u64 t; cvta.to.shared.u64 t, %1; cvt.u32.u64 %0, t; }"
        : "=r"(a) : "l"(p));
    return a;
}
__device__ __forceinline__ void mma16816(float* d, const uint32_t* a, const uint32_t* b) {
    asm volatile(
        "mma.sync.aligned.m16n8k16.row.col.f32.f16.f16.f32 "
        "{%0,%1,%2,%3}, {%4,%5,%6,%7}, {%8,%9}, {%0,%1,%2,%3};"
        : "+f"(d[0]), "+f"(d[1]), "+f"(d[2]), "+f"(d[3])
        : "r"(a[0]), "r"(a[1]), "r"(a[2]), "r"(a[3]), "r"(b[0]), "r"(b[1]));
}
#define LDMX4(r, addr) \
    asm volatile("ldmatrix.sync.aligned.m8n8.x4.shared.b16 {%0,%1,%2,%3}, [%4];" \
                 : "=r"((r)[0]), "=r"((r)[1]), "=r"((r)[2]), "=r"((r)[3]) : "r"(addr))
#define LDMX4T(r, addr) \
    asm volatile("ldmatrix.sync.aligned.m8n8.x4.trans.shared.b16 {%0,%1,%2,%3}, [%4];" \
                 : "=r"((r)[0]), "=r"((r)[1]), "=r"((r)[2]), "=r"((r)[3]) : "r"(addr))
#define CPA16(s, gp) \
    asm volatile("cp.async.cg.shared.global [%0], [%1], 16;" :: "r"(s), "l"(gp))

// ---------------- hist + tile tables ----------------------------------------
__global__ void hist_kernel(const int* __restrict__ batch) {
    __shared__ int cnt[NGRAPH];
    int tid = threadIdx.x;
    if (tid < NGRAPH) cnt[tid] = 0;
    __syncthreads();
    for (int i = tid; i < N_TOK; i += 256) atomicAdd(&cnt[batch[i]], 1);
    __syncthreads();
    if (tid == 0) {
        int off = 0;
        for (int g = 0; g < NGRAPH; g++) {
            g_off[g] = off; g_sizes[g] = cnt[g]; off += cnt[g];
        }
        g_off[NGRAPH] = off;
        int t = 0;
        for (int g = 0; g < NGRAPH; g++) {
            int S = g_sizes[g];
            for (int i = 0; i < S; i += 128) {
                g_tile_g[t] = g;
                g_tile_tok0[t] = g_off[g] + i;
                g_tile_nval[t] = (S - i < 128) ? (S - i) : 128;
                t++;
            }
        }
        for (; t < TILEMAX; t++) g_tile_nval[t] = 0;
    }
}

__device__ __forceinline__ void split2(float f0, float f1, ushort2& uh, ushort2& ul) {
    __half h0 = __float2half_rn(f0), h1 = __float2half_rn(f1);
    __half l0 = __float2half_rn(f0 - __half2float(h0));
    __half l1 = __float2half_rn(f1 - __half2float(h1));
    uh = make_ushort2(__half_as_ushort(h0), __half_as_ushort(h1));
    ul = make_ushort2(__half_as_ushort(l0), __half_as_ushort(l1));
}
__device__ __forceinline__ ushort4 round4(float4 v) {
    ushort4 r;
    r.x = __half_as_ushort(__float2half_rn(v.x));
    r.y = __half_as_ushort(__float2half_rn(v.y));
    r.z = __half_as_ushort(__float2half_rn(v.z));
    r.w = __half_as_ushort(__float2half_rn(v.w));
    return r;
}

// fp32 -> fp16 round, x4
__global__ void conv_round_kernel(const float* __restrict__ src,
                                  __half* __restrict__ dst, long n4) {
    long i = (long)blockIdx.x * blockDim.x + threadIdx.x;
    long stride = (long)gridDim.x * blockDim.x;
    for (; i < n4; i += stride)
        ((ushort4*)dst)[i] = round4(((const float4*)src)[i]);
}

// weights: fp16 rounding, one launch
__global__ void conv_w_kernel(const float* __restrict__ w1,
                              const float* __restrict__ w2) {
    const long n1 = (long)QKV3 * KDIM / 4;
    const long n2 = (long)DIM * KDIM / 4;
    long i = (long)blockIdx.x * blockDim.x + threadIdx.x;
    long stride = (long)gridDim.x * blockDim.x;
    for (; i < n1 + n2; i += stride) {
        if (i < n1) ((ushort4*)g_b1_hi)[i]      = round4(((const float4*)w1)[i]);
        else        ((ushort4*)g_b2_hi)[i - n1] = round4(((const float4*)w2)[i - n1]);
    }
}

#define TEN_BYTES (128 * 144)

__device__ __forceinline__ void issue_slab(uint32_t sdst, const __half* g,
                                           int k0, int tid) {
#pragma unroll
    for (int t = 0; t < 4; t++) {
        int id  = tid + t * 256;
        int row = id >> 3, col = id & 7;
        CPA16(sdst + row * 144 + col * 16, g + (size_t)row * KDIM + k0 + col * 8);
    }
}

// ---------------- GEMM1: qkv = x16 @ w16^T (1-term fp16, 3-stage ring) ------
// epilogue: q scale->split, k LN(ln1)->split, v LN(ln2)->split
#define QK_SMEM (3 * 2 * TEN_BYTES)   // 110592 -> 2 CTAs/SM

__global__ __launch_bounds__(256, 2)
void qkv_gemm_kernel(const __half* __restrict__ Ah, const __half* __restrict__ Bh,
                     const int* __restrict__ batch,
                     const float* __restrict__ ln1w, const float* __restrict__ ln1b,
                     const float* __restrict__ ln2w, const float* __restrict__ ln2b) {
    extern __shared__ __align__(16) char smem[];
    uint32_t sb = smem_u32(smem);
    int tid = threadIdx.x, wid = tid >> 5, lane = tid & 31;
    int warpM = (wid & 3) * 32;
    int warpN = (wid >> 2) * 64;
    int g = lane >> 2, c2 = lane & 3;

    uint32_t aoff = (lane & 15) * 144 + (lane >> 4) * 16;
    uint32_t boff = ((lane & 7) + ((lane >> 4) << 3)) * 144 + ((lane >> 3) & 1) * 16;

    const __half* pAh = Ah + (size_t)blockIdx.y * 128 * KDIM;
    const __half* pBh = Bh + (size_t)blockIdx.x * 128 * KDIM;

#define QST(s, t) (sb + ((s) * 2 + (t)) * TEN_BYTES)
#define Q_ISSUE(s, k0)                            \
    do {                                          \
        issue_slab(QST(s, 0), pAh, (k0), tid);    \
        issue_slab(QST(s, 1), pBh, (k0), tid);    \
        asm volatile("cp.async.commit_group;");   \
    } while (0)

    Q_ISSUE(0, 0);
    Q_ISSUE(1, 64);

    float acc[2][8][4];
#pragma unroll
    for (int i = 0; i < 2; i++)
#pragma unroll
        for (int j = 0; j < 8; j++)
#pragma unroll
            for (int k = 0; k < 4; k++) acc[i][j][k] = 0.0f;

    for (int it = 0; it < 8; it++) {
        int s = it % 3;
        if (it < 7) asm volatile("cp.async.wait_group 1;");
        else        asm volatile("cp.async.wait_group 0;");
        __syncthreads();   // single barrier: also frees stage (it-1)%3 = (it+2)%3
        uint32_t aA0 = QST(s, 0) + warpM * 144 + aoff;
        uint32_t aB0 = QST(s, 1) + warpN * 144 + boff;
#pragma unroll
        for (int kk = 0; kk < 4; kk++) {
            int ko = kk * 32;
            uint32_t ah[2][4], bf[4][4];
            LDMX4(ah[0], aA0 + ko); LDMX4(ah[1], aA0 + 16 * 144 + ko);
#pragma unroll
            for (int p = 0; p < 4; p++) LDMX4(bf[p], aB0 + p * 16 * 144 + ko);
#pragma unroll
            for (int mt = 0; mt < 2; mt++)
#pragma unroll
                for (int nt = 0; nt < 8; nt++)
                    mma16816(acc[mt][nt], ah[mt], &bf[nt >> 1][(nt & 1) * 2]);
        }
        if (it + 2 < 8) Q_ISSUE((it + 2) % 3, (it + 2) * 64);
    }

    // epilogue: q scale+split / k,v LN+split
    int mode = blockIdx.x >> 2;          // 0 q, 1 k, 2 v
    const float* lw = (mode == 1) ? ln1w : ln2w;
    const float* lb = (mode == 1) ? ln1b : ln2b;
    __half* dh = (mode == 0) ? g_q_hi : (mode == 1) ? g_k_hi : g_v_hi;
    __half* dl = (mode == 0) ? g_q_lo : (mode == 1) ? g_k_lo : g_v_lo;
    int colbase = blockIdx.x * 128 - mode * 512 + warpN;   // 0..511 in buffer
#pragma unroll
    for (int mt = 0; mt < 2; mt++) {
#pragma unroll
        for (int hf = 0; hf < 2; hf++) {
            size_t m = (size_t)blockIdx.y * 128 + warpM + mt * 16 + g + hf * 8;
            float v[16];
#pragma unroll
            for (int nt = 0; nt < 8; nt++) {
                v[nt * 2]     = acc[mt][nt][hf * 2];
                v[nt * 2 + 1] = acc[mt][nt][hf * 2 + 1];
            }
            if (mode == 0) {
                int n = (int)(m & (N_TOK - 1));
                float sc = 1.0f / (float)g_sizes[batch[n]];
#pragma unroll
                for (int k = 0; k < 16; k++) v[k] *= sc;
            } else {
                float s = 0.f, s2 = 0.f;
#pragma unroll
                for (int k = 0; k < 16; k++) { s += v[k]; s2 += v[k] * v[k]; }
                s  += __shfl_xor_sync(0xffffffffu, s, 1);
                s  += __shfl_xor_sync(0xffffffffu, s, 2);
                s2 += __shfl_xor_sync(0xffffffffu, s2, 1);
                s2 += __shfl_xor_sync(0xffffffffu, s2, 2);
                float mu = s * (1.0f / 64.0f);
                float var = s2 * (1.0f / 64.0f) - mu * mu;
                float rs = rsqrtf(var + 1e-6f);
#pragma unroll
                for (int nt = 0; nt < 8; nt++) {
                    int cl = ((warpN + nt * 8 + c2 * 2) & 63); // head-local
                    v[nt * 2]     = (v[nt * 2]     - mu) * rs * lw[cl]     + lb[cl];
                    v[nt * 2 + 1] = (v[nt * 2 + 1] - mu) * rs * lw[cl + 1] + lb[cl + 1];
                }
            }
            size_t base = m * DIM + colbase + c2 * 2;
#pragma unroll
            for (int nt = 0; nt < 8; nt++) {
                ushort2 uh, ul;
                split2(v[nt * 2], v[nt * 2 + 1], uh, ul);
                *(ushort2*)((unsigned short*)dh + base + nt * 8) = uh;
                *(ushort2*)((unsigned short*)dl + base + nt * 8) = ul;
            }
        }
    }
#undef QST
#undef Q_ISSUE
}

// ---------------- GEMM2: out = (attn_hi+attn_lo) @ w_out^T + bias -----------
// 2-term, 2-stage, interleaved term order (R7 schedule)
#define OG_SMEM (2 * 3 * TEN_BYTES)   // 110592 -> 2 CTAs/SM

__global__ __launch_bounds__(256, 2)
void out_gemm_kernel(const __half* __restrict__ Ah, const __half* __restrict__ Al,
                     const __half* __restrict__ Bh,
                     float* __restrict__ C, const float* __restrict__ bias) {
    extern __shared__ __align__(16) char smem[];
    uint32_t sb = smem_u32(smem);
    int tid = threadIdx.x, wid = tid >> 5, lane = tid & 31;
    int warpM = (wid & 3) * 32;
    int warpN = (wid >> 2) * 64;
    int g = lane >> 2, c2 = lane & 3;

    uint32_t aoff = (lane & 15) * 144 + (lane >> 4) * 16;
    uint32_t boff = ((lane & 7) + ((lane >> 4) << 3)) * 144 + ((lane >> 3) & 1) * 16;

    const __half* pAh = Ah + (size_t)blockIdx.y * 128 * KDIM;
    const __half* pAl = Al + (size_t)blockIdx.y * 128 * KDIM;
    const __half* pBh = Bh + (size_t)blockIdx.x * 128 * KDIM;

#define OST(s, t) (sb + ((s) * 3 + (t)) * TEN_BYTES)
#define O_ISSUE(s, k0)                            \
    do {                                          \
        issue_slab(OST(s, 0), pAh, (k0), tid);    \
        issue_slab(OST(s, 1), pAl, (k0), tid);    \
        issue_slab(OST(s, 2), pBh, (k0), tid);    \
        asm volatile("cp.async.commit_group;");   \
    } while (0)

    O_ISSUE(0, 0);
    O_ISSUE(1, 64);

    float acc[2][8][4];
#pragma unroll
    for (int i = 0; i < 2; i++)
#pragma unroll
        for (int j = 0; j < 8; j++)
#pragma unroll
            for (int k = 0; k < 4; k++) acc[i][j][k] = 0.0f;

    for (int it = 0; it < 8; it++) {
        int s = it & 1;
        if (it < 7) asm volatile("cp.async.wait_group 1;");
        else        asm volatile("cp.async.wait_group 0;");
        __syncthreads();
        uint32_t aA0 = OST(s, 0) + warpM * 144 + aoff;
        uint32_t aL0 = OST(s, 1) + warpM * 144 + aoff;
        uint32_t aB0 = OST(s, 2) + warpN * 144 + boff;
#pragma unroll
        for (int kk = 0; kk < 4; kk++) {
            int ko = kk * 32;
            uint32_t ah[2][4], al[2][4], bf[4][4];
            LDMX4(ah[0], aA0 + ko); LDMX4(ah[1], aA0 + 16 * 144 + ko);
            LDMX4(al[0], aL0 + ko); LDMX4(al[1], aL0 + 16 * 144 + ko);
#pragma unroll
            for (int p = 0; p < 4; p++) LDMX4(bf[p], aB0 + p * 16 * 144 + ko);
#pragma unroll
            for (int mt = 0; mt < 2; mt++)
#pragma unroll
                for (int nt = 0; nt < 8; nt++) {
                    const uint32_t* b = &bf[nt >> 1][(nt & 1) * 2];
                    mma16816(acc[mt][nt], ah[mt], b);
                    mma16816(acc[mt][nt], al[mt], b);
                }
        }
        __syncthreads();
        if (it + 2 < 8) O_ISSUE(s, (it + 2) * 64);
    }

#pragma unroll
    for (int mt = 0; mt < 2; mt++) {
        size_t m0 = (size_t)blockIdx.y * 128 + warpM + mt * 16 + g;
#pragma unroll
        for (int nt = 0; nt < 8; nt++) {
            int nc = blockIdx.x * 128 + warpN + nt * 8 + c2 * 2;
            float b0 = bias[nc], b1 = bias[nc + 1];
            *(float2*)(C + m0 * DIM + nc) =
                make_float2(acc[mt][nt][0] + b0, acc[mt][nt][1] + b1);
            *(float2*)(C + (m0 + 8) * DIM + nc) =
                make_float2(acc[mt][nt][2] + b0, acc[mt][nt][3] + b1);
        }
    }
#undef OST
#undef O_ISSUE
}

// ---------------- ktvT[b,h,g] (tensor, 3-term, ldmatrix.trans) --------------
#define KT_SLAB  (64 * 144)
#define KT_STAGE (4 * KT_SLAB)
#define KT_SMEM  (2 * KT_STAGE)      // 73728

__global__ __launch_bounds__(128, 2)
void ktvmma_kernel() {
    int gseg = blockIdx.x & 31;
    int h = (blockIdx.x >> 5) & 7;
    int b = blockIdx.x >> 8;
    int s0 = g_off[gseg], s1 = g_off[gseg + 1];
    int NCH = (s1 - s0 + 63) >> 6;
    if (NCH <= 0) NCH = 1;

    extern __shared__ __align__(16) char smem[];
    uint32_t sb = smem_u32(smem);
    int tid = threadIdx.x, wid = tid >> 5, lane = tid & 31;
    int lg = lane >> 2, c2 = lane & 3;

#define KT_ISSUE(st, c)                                                        \
    do {                                                                       \
        int t0 = s0 + (c) * 64;                                                \
        uint32_t base = sb + (st) * KT_STAGE;                                  \
        char* cbase = smem + (st) * KT_STAGE;                                  \
        _Pragma("unroll")                                                      \
        for (int i = 0; i < 4; i++) {                                          \
            int id = tid + i * 128;                                            \
            int row = id >> 3, ch = id & 7;                                    \
            int tok = t0 + row;                                                \
            uint32_t so = row * 144 + ch * 16;                                 \
            if (tok < s1) {                                                    \
                size_t go = ((size_t)b * N_TOK + tok) * DIM + h * DH + ch * 8; \
                CPA16(base + 0 * KT_SLAB + so, g_k_hi + go);                   \
                CPA16(base + 1 * KT_SLAB + so, g_k_lo + go);                   \
                CPA16(base + 2 * KT_SLAB + so, g_v_hi + go);                   \
                CPA16(base + 3 * KT_SLAB + so, g_v_lo + go);                   \
            } else {                                                           \
                uint4 z = make_uint4(0, 0, 0, 0);                              \
                *(uint4*)(cbase + 0 * KT_SLAB + so) = z;                       \
                *(uint4*)(cbase + 1 * KT_SLAB + so) = z;                       \
                *(uint4*)(cbase + 2 * KT_SLAB + so) = z;                       \
                *(uint4*)(cbase + 3 * KT_SLAB + so) = z;                       \
            }                                                                  \
        }                                                                      \
        asm volatile("cp.async.commit_group;");                                \
    } while (0)

    KT_ISSUE(0, 0);
    if (NCH > 1) KT_ISSUE(1, 1);

    uint32_t aoffT = ((lane & 7) + (lane >> 4) * 8) * 144 + ((lane >> 3) & 1) * 16;
    uint32_t boffT = ((lane & 7) + ((lane >> 3) & 1) * 8) * 144 + (lane >> 4) * 16;

    float acc[8][4];
#pragma unroll
    for (int j = 0; j < 8; j++)
#pragma unroll
        for (int k = 0; k < 4; k++) acc[j][k] = 0.0f;

    for (int c = 0; c < NCH; c++) {
        int st = c & 1;
        if (c + 2 <= NCH) asm volatile("cp.async.wait_group 1;");
        else              asm volatile("cp.async.wait_group 0;");
        __syncthreads();
        uint32_t base = sb + st * KT_STAGE;
        uint32_t aKh = base + 0 * KT_SLAB + boffT;
        uint32_t aKl = base + 1 * KT_SLAB + boffT;
        uint32_t aVh = base + 2 * KT_SLAB + wid * 32 + aoffT;
        uint32_t aVl = base + 3 * KT_SLAB + wid * 32 + aoffT;
#pragma unroll
        for (int kk = 0; kk < 4; kk++) {
            int ko = kk * (16 * 144);
            uint32_t vh[4], vl[4], kh[4][4], kl[4][4];
            LDMX4T(vh, aVh + ko);
            LDMX4T(vl, aVl + ko);
#pragma unroll
            for (int nb = 0; nb < 4; nb++) {
                LDMX4T(kh[nb], aKh + nb * 32 + ko);
                LDMX4T(kl[nb], aKl + nb * 32 + ko);
            }
#pragma unroll
            for (int nt = 0; nt < 8; nt++) {
                mma16816(acc[nt], vh, &kh[nt >> 1][(nt & 1) * 2]);
                mma16816(acc[nt], vl, &kh[nt >> 1][(nt & 1) * 2]);
                mma16816(acc[nt], vh, &kl[nt >> 1][(nt & 1) * 2]);
            }
        }
        __syncthreads();
        if (c + 2 < NCH) KT_ISSUE(st, c + 2);
    }

    size_t kb = (size_t)blockIdx.x * (DH * DH);
    int r0 = wid * 16 + lg;
#pragma unroll
    for (int nt = 0; nt < 8; nt++) {
        int cidx = nt * 8 + c2 * 2;
        ushort2 uh, ul;
        split2(acc[nt][0], acc[nt][1], uh, ul);
        *(ushort2*)((unsigned short*)g_ktvT_hi + kb + (size_t)r0 * DH + cidx) = uh;
        *(ushort2*)((unsigned short*)g_ktvT_lo + kb + (size_t)r0 * DH + cidx) = ul;
        split2(acc[nt][2], acc[nt][3], uh, ul);
        *(ushort2*)((unsigned short*)g_ktvT_hi + kb + (size_t)(r0 + 8) * DH + cidx) = uh;
        *(ushort2*)((unsigned short*)g_ktvT_lo + kb + (size_t)(r0 + 8) * DH + cidx) = ul;
    }
#undef KT_ISSUE
}

// ---------------- attn tile = q_tile @ ktvT (tensor, 3-term) ----------------
#define AP_QSLAB (128 * 144)
#define AP_TSLAB (64 * 144)
#define AP_SMEM  (2 * AP_QSLAB + 2 * AP_TSLAB)   // 55296

__global__ __launch_bounds__(256, 2)
void applymma_kernel() {
    int h = blockIdx.x, ti = blockIdx.y, b = blockIdx.z;
    int nval = g_tile_nval[ti];
    if (nval == 0) return;
    int gseg = g_tile_g[ti];
    int tok0 = g_tile_tok0[ti];

    extern __shared__ __align__(16) char smem[];
    uint32_t sb = smem_u32(smem);
    uint32_t sQh = sb, sQl = sb + AP_QSLAB;
    uint32_t sTh = sb + 2 * AP_QSLAB, sTl = sTh + AP_TSLAB;

    int tid = threadIdx.x, wid = tid >> 5, lane = tid & 31;
    int warpM = (wid & 3) * 32;
    int warpN = (wid >> 2) * 32;
    int g = lane >> 2, c2 = lane & 3;

    {
        size_t qrow0 = (size_t)b * N_TOK + tok0;
#pragma unroll
        for (int t = 0; t < 4; t++) {
            int id = tid + t * 256;          // 0..1023
            int row = id >> 3, ch = id & 7;
            size_t go = (qrow0 + row) * DIM + h * DH + ch * 8;
            CPA16(sQh + row * 144 + ch * 16, (const __half*)g_q_hi + go);
            CPA16(sQl + row * 144 + ch * 16, (const __half*)g_q_lo + go);
        }
        size_t kbase = ((size_t)((b * HEADS + h) * NGRAPH + gseg)) * DH * DH;
#pragma unroll
        for (int t = 0; t < 2; t++) {
            int id = tid + t * 256;          // 0..511
            int row = id >> 3, ch = id & 7;
            size_t ko = kbase + (size_t)row * DH + ch * 8;
            CPA16(sTh + row * 144 + ch * 16, (const __half*)g_ktvT_hi + ko);
            CPA16(sTl + row * 144 + ch * 16, (const __half*)g_ktvT_lo + ko);
        }
        asm volatile("cp.async.commit_group;");
        asm volatile("cp.async.wait_group 0;");
        __syncthreads();
    }

    uint32_t aoff = (lane & 15) * 144 + (lane >> 4) * 16;
    uint32_t boff = ((lane & 7) + ((lane >> 4) << 3)) * 144 + ((lane >> 3) & 1) * 16;

    float acc[2][4][4];
#pragma unroll
    for (int i = 0; i < 2; i++)
#pragma unroll
        for (int j = 0; j < 4; j++)
#pragma unroll
            for (int k = 0; k < 4; k++) acc[i][j][k] = 0.0f;

    uint32_t aQh = sQh + warpM * 144 + aoff;
    uint32_t aQl = sQl + warpM * 144 + aoff;
    uint32_t aTh = sTh + warpN * 144 + boff;
    uint32_t aTl = sTl + warpN * 144 + boff;

#pragma unroll
    for (int kk = 0; kk < 4; kk++) {
        int ko = kk * 32;
        uint32_t qh[2][4], ql[2][4], bh[2][4], bl[2][4];
        LDMX4(qh[0], aQh + ko); LDMX4(qh[1], aQh + 16 * 144 + ko);
        LDMX4(ql[0], aQl + ko); LDMX4(ql[1], aQl + 16 * 144 + ko);
        LDMX4(bh[0], aTh + ko); LDMX4(bh[1], aTh + 16 * 144 + ko);
        LDMX4(bl[0], aTl + ko); LDMX4(bl[1], aTl + 16 * 144 + ko);
#pragma unroll
        for (int mt = 0; mt < 2; mt++)
#pragma unroll
            for (int nt = 0; nt < 4; nt++) {
                const uint32_t* bph = &bh[nt >> 1][(nt & 1) * 2];
                const uint32_t* bpl = &bl[nt >> 1][(nt & 1) * 2];
                mma16816(acc[mt][nt], qh[mt], bph);
                mma16816(acc[mt][nt], ql[mt], bph);
                mma16816(acc[mt][nt], qh[mt], bpl);
            }
    }

    // masked epilogue -> attn hi/lo
#pragma unroll
    for (int mt = 0; mt < 2; mt++) {
#pragma unroll
        for (int hf = 0; hf < 2; hf++) {
            int r = warpM + mt * 16 + g + hf * 8;
            if (r < nval) {
                size_t base = ((size_t)b * N_TOK + tok0 + r) * DIM + h * DH + warpN + c2 * 2;
#pragma unroll
                for (int nt = 0; nt < 4; nt++) {
                    ushort2 uh, ul;
                    split2(acc[mt][nt][hf * 2], acc[mt][nt][hf * 2 + 1], uh, ul);
                    *(ushort2*)((unsigned short*)g_attn_hi + base + nt * 8) = uh;
                    *(ushort2*)((unsigned short*)g_attn_lo + base + nt * 8) = ul;
                }
            }
        }
    }
}

// ---------------- launch ----------------------------------------------------
extern "C" void kernel_launch(void* const* d_in, const int* in_sizes, int n_in,
                              void* d_out, int out_size) {
    const float* x     = (const float*)d_in[0];
    const float* w_qkv = (const float*)d_in[1];
    const float* ln1w  = (const float*)d_in[2];
    const float* ln1b  = (const float*)d_in[3];
    const float* ln2w  = (const float*)d_in[4];
    const float* ln2b  = (const float*)d_in[5];
    const float* w_out = (const float*)d_in[6];
    const float* b_out = (const float*)d_in[7];
    const int*   batch = (const int*)d_in[8];
    float* out = (float*)d_out;

    __half *ah_p, *b1h_p, *b2h_p, *ath_p, *atl_p;
    cudaGetSymbolAddress((void**)&ah_p,  g_a_hi);
    cudaGetSymbolAddress((void**)&b1h_p, g_b1_hi);
    cudaGetSymbolAddress((void**)&b2h_p, g_b2_hi);
    cudaGetSymbolAddress((void**)&ath_p, g_attn_hi);
    cudaGetSymbolAddress((void**)&atl_p, g_attn_lo);

    cudaFuncSetAttribute(qkv_gemm_kernel, cudaFuncAttributeMaxDynamicSharedMemorySize, QK_SMEM);
    cudaFuncSetAttribute(out_gemm_kernel, cudaFuncAttributeMaxDynamicSharedMemorySize, OG_SMEM);
    cudaFuncSetAttribute(ktvmma_kernel,   cudaFuncAttributeMaxDynamicSharedMemorySize, KT_SMEM);
    cudaFuncSetAttribute(applymma_kernel, cudaFuncAttributeMaxDynamicSharedMemorySize, AP_SMEM);

    // 0) segment offsets + tile tables
    hist_kernel<<<1, 256>>>(batch);

    // 1) conversions (x: round only; weights: round)
    conv_round_kernel<<<4096, 256>>>(x, ah_p, (long)M_ROWS * KDIM / 4);
    conv_w_kernel<<<1024, 256>>>(w_qkv, w_out);

    // 2) qkv GEMM (1-term fp16, 3-stage) + fused epilogue
    qkv_gemm_kernel<<<dim3(QKV3 / 128, M_ROWS / 128), 256, QK_SMEM>>>(
        ah_p, b1h_p, batch, ln1w, ln1b, ln2w, ln2b);

    // 3) ktvT per (b,h,g) (tensor, 3-term)
    ktvmma_kernel<<<B_SZ * HEADS * NGRAPH, 128, KT_SMEM>>>();

    // 4) attn = qn @ ktv (tensor, masked ragged tiles)
    applymma_kernel<<<dim3(HEADS, TILEMAX, B_SZ), 256, AP_SMEM>>>();

    // 5) out = attn @ w_outT + bias (2-term, interleaved)
    out_gemm_kernel<<<dim3(DIM / 128, M_ROWS / 128), 256, OG_SMEM>>>(
        ath_p, atl_p, b2h_p, out, b_out);
}

// round 11
// speedup vs baseline: 5.4748x; 1.1202x over previous
#include <cuda_runtime.h>
#include <cuda_fp16.h>
#include <cstdint>

// ---------------- problem constants (fixed by setup_inputs) ----------------
#define B_SZ   2
#define N_TOK  32768
#define DIM    512
#define HEADS  8
#define DH     64
#define NGRAPH 32
#define QKV3   1536
#define M_ROWS (B_SZ * N_TOK)          // 65536
#define KDIM   512
#define TILEMAX 288                    // max token-tiles per batch

// ---------------- device scratch (static; no allocations allowed) ----------
__device__ __half g_a_hi[(size_t)M_ROWS * KDIM];
__device__ __half g_b1_hi[QKV3 * KDIM];
__device__ __half g_b2_hi[DIM * KDIM];
__device__ __half g_q_hi[((size_t)M_ROWS + 128) * DIM];   // +128 slack rows
__device__ __half g_q_lo[((size_t)M_ROWS + 128) * DIM];
__device__ __half g_k_hi[(size_t)M_ROWS * DIM];
__device__ __half g_k_lo[(size_t)M_ROWS * DIM];
__device__ __half g_v_hi[(size_t)M_ROWS * DIM];
__device__ __half g_v_lo[(size_t)M_ROWS * DIM];
__device__ __half g_attn_hi[(size_t)M_ROWS * DIM];
__device__ __half g_ktvT_hi[B_SZ * HEADS * NGRAPH * DH * DH];
__device__ __half g_ktvT_lo[B_SZ * HEADS * NGRAPH * DH * DH];
__device__ int    g_sizes[NGRAPH];
__device__ int    g_off [NGRAPH + 1];
__device__ int    g_tile_g[TILEMAX];
__device__ int    g_tile_tok0[TILEMAX];
__device__ int    g_tile_nval[TILEMAX];

// ---------------- helpers ---------------------------------------------------
__device__ __forceinline__ uint32_t smem_u32(const void* p) {
    uint32_t a;
    asm("{ .reg .u64 t; cvta.to.shared.u64 t, %1; cvt.u32.u64 %0, t; }"
        : "=r"(a) : "l"(p));
    return a;
}
__device__ __forceinline__ void mma16816(float* d, const uint32_t* a, const uint32_t* b) {
    asm volatile(
        "mma.sync.aligned.m16n8k16.row.col.f32.f16.f16.f32 "
        "{%0,%1,%2,%3}, {%4,%5,%6,%7}, {%8,%9}, {%0,%1,%2,%3};"
        : "+f"(d[0]), "+f"(d[1]), "+f"(d[2]), "+f"(d[3])
        : "r"(a[0]), "r"(a[1]), "r"(a[2]), "r"(a[3]), "r"(b[0]), "r"(b[1]));
}
#define LDMX4(r, addr) \
    asm volatile("ldmatrix.sync.aligned.m8n8.x4.shared.b16 {%0,%1,%2,%3}, [%4];" \
                 : "=r"((r)[0]), "=r"((r)[1]), "=r"((r)[2]), "=r"((r)[3]) : "r"(addr))
#define LDMX4T(r, addr) \
    asm volatile("ldmatrix.sync.aligned.m8n8.x4.trans.shared.b16 {%0,%1,%2,%3}, [%4];" \
                 : "=r"((r)[0]), "=r"((r)[1]), "=r"((r)[2]), "=r"((r)[3]) : "r"(addr))
#define CPA16(s, gp) \
    asm volatile("cp.async.cg.shared.global [%0], [%1], 16;" :: "r"(s), "l"(gp))

// ---------------- hist + tile tables ----------------------------------------
__global__ void hist_kernel(const int* __restrict__ batch) {
    __shared__ int cnt[NGRAPH];
    int tid = threadIdx.x;
    if (tid < NGRAPH) cnt[tid] = 0;
    __syncthreads();
    for (int i = tid; i < N_TOK; i += 256) atomicAdd(&cnt[batch[i]], 1);
    __syncthreads();
    if (tid == 0) {
        int off = 0;
        for (int g = 0; g < NGRAPH; g++) {
            g_off[g] = off; g_sizes[g] = cnt[g]; off += cnt[g];
        }
        g_off[NGRAPH] = off;
        int t = 0;
        for (int g = 0; g < NGRAPH; g++) {
            int S = g_sizes[g];
            for (int i = 0; i < S; i += 128) {
                g_tile_g[t] = g;
                g_tile_tok0[t] = g_off[g] + i;
                g_tile_nval[t] = (S - i < 128) ? (S - i) : 128;
                t++;
            }
        }
        for (; t < TILEMAX; t++) g_tile_nval[t] = 0;
    }
}

__device__ __forceinline__ void split2(float f0, float f1, ushort2& uh, ushort2& ul) {
    __half h0 = __float2half_rn(f0), h1 = __float2half_rn(f1);
    __half l0 = __float2half_rn(f0 - __half2float(h0));
    __half l1 = __float2half_rn(f1 - __half2float(h1));
    uh = make_ushort2(__half_as_ushort(h0), __half_as_ushort(h1));
    ul = make_ushort2(__half_as_ushort(l0), __half_as_ushort(l1));
}
__device__ __forceinline__ ushort4 round4(float4 v) {
    ushort4 r;
    r.x = __half_as_ushort(__float2half_rn(v.x));
    r.y = __half_as_ushort(__float2half_rn(v.y));
    r.z = __half_as_ushort(__float2half_rn(v.z));
    r.w = __half_as_ushort(__float2half_rn(v.w));
    return r;
}

// fp32 -> fp16 round, x4
__global__ void conv_round_kernel(const float* __restrict__ src,
                                  __half* __restrict__ dst, long n4) {
    long i = (long)blockIdx.x * blockDim.x + threadIdx.x;
    long stride = (long)gridDim.x * blockDim.x;
    for (; i < n4; i += stride)
        ((ushort4*)dst)[i] = round4(((const float4*)src)[i]);
}

// weights: fp16 rounding, one launch
__global__ void conv_w_kernel(const float* __restrict__ w1,
                              const float* __restrict__ w2) {
    const long n1 = (long)QKV3 * KDIM / 4;
    const long n2 = (long)DIM * KDIM / 4;
    long i = (long)blockIdx.x * blockDim.x + threadIdx.x;
    long stride = (long)gridDim.x * blockDim.x;
    for (; i < n1 + n2; i += stride) {
        if (i < n1) ((ushort4*)g_b1_hi)[i]      = round4(((const float4*)w1)[i]);
        else        ((ushort4*)g_b2_hi)[i - n1] = round4(((const float4*)w2)[i - n1]);
    }
}

#define TEN_BYTES (128 * 144)

__device__ __forceinline__ void issue_slab(uint32_t sdst, const __half* g,
                                           int k0, int tid) {
#pragma unroll
    for (int t = 0; t < 4; t++) {
        int id  = tid + t * 256;
        int row = id >> 3, col = id & 7;
        CPA16(sdst + row * 144 + col * 16, g + (size_t)row * KDIM + k0 + col * 8);
    }
}

// ---------------- GEMM1: qkv = x16 @ w16^T (1-term fp16, 3-stage ring) ------
// epilogue: q scale->split, k LN(ln1)->split, v LN(ln2)->split
#define QK_SMEM (3 * 2 * TEN_BYTES)   // 110592 -> 2 CTAs/SM

__global__ __launch_bounds__(256, 2)
void qkv_gemm_kernel(const __half* __restrict__ Ah, const __half* __restrict__ Bh,
                     const int* __restrict__ batch,
                     const float* __restrict__ ln1w, const float* __restrict__ ln1b,
                     const float* __restrict__ ln2w, const float* __restrict__ ln2b) {
    extern __shared__ __align__(16) char smem[];
    uint32_t sb = smem_u32(smem);
    int tid = threadIdx.x, wid = tid >> 5, lane = tid & 31;
    int warpM = (wid & 3) * 32;
    int warpN = (wid >> 2) * 64;
    int g = lane >> 2, c2 = lane & 3;

    uint32_t aoff = (lane & 15) * 144 + (lane >> 4) * 16;
    uint32_t boff = ((lane & 7) + ((lane >> 4) << 3)) * 144 + ((lane >> 3) & 1) * 16;

    const __half* pAh = Ah + (size_t)blockIdx.y * 128 * KDIM;
    const __half* pBh = Bh + (size_t)blockIdx.x * 128 * KDIM;

#define QST(s, t) (sb + ((s) * 2 + (t)) * TEN_BYTES)
#define Q_ISSUE(s, k0)                            \
    do {                                          \
        issue_slab(QST(s, 0), pAh, (k0), tid);    \
        issue_slab(QST(s, 1), pBh, (k0), tid);    \
        asm volatile("cp.async.commit_group;");   \
    } while (0)

    Q_ISSUE(0, 0);
    Q_ISSUE(1, 64);

    float acc[2][8][4];
#pragma unroll
    for (int i = 0; i < 2; i++)
#pragma unroll
        for (int j = 0; j < 8; j++)
#pragma unroll
            for (int k = 0; k < 4; k++) acc[i][j][k] = 0.0f;

    for (int it = 0; it < 8; it++) {
        int s = it % 3;
        if (it < 7) asm volatile("cp.async.wait_group 1;");
        else        asm volatile("cp.async.wait_group 0;");
        __syncthreads();   // single barrier: also frees stage (it-1)%3 = (it+2)%3
        uint32_t aA0 = QST(s, 0) + warpM * 144 + aoff;
        uint32_t aB0 = QST(s, 1) + warpN * 144 + boff;
#pragma unroll
        for (int kk = 0; kk < 4; kk++) {
            int ko = kk * 32;
            uint32_t ah[2][4], bf[4][4];
            LDMX4(ah[0], aA0 + ko); LDMX4(ah[1], aA0 + 16 * 144 + ko);
#pragma unroll
            for (int p = 0; p < 4; p++) LDMX4(bf[p], aB0 + p * 16 * 144 + ko);
#pragma unroll
            for (int mt = 0; mt < 2; mt++)
#pragma unroll
                for (int nt = 0; nt < 8; nt++)
                    mma16816(acc[mt][nt], ah[mt], &bf[nt >> 1][(nt & 1) * 2]);
        }
        if (it + 2 < 8) Q_ISSUE((it + 2) % 3, (it + 2) * 64);
    }

    // epilogue: q scale+split / k,v LN+split
    int mode = blockIdx.x >> 2;          // 0 q, 1 k, 2 v
    const float* lw = (mode == 1) ? ln1w : ln2w;
    const float* lb = (mode == 1) ? ln1b : ln2b;
    __half* dh = (mode == 0) ? g_q_hi : (mode == 1) ? g_k_hi : g_v_hi;
    __half* dl = (mode == 0) ? g_q_lo : (mode == 1) ? g_k_lo : g_v_lo;
    int colbase = blockIdx.x * 128 - mode * 512 + warpN;   // 0..511 in buffer
#pragma unroll
    for (int mt = 0; mt < 2; mt++) {
#pragma unroll
        for (int hf = 0; hf < 2; hf++) {
            size_t m = (size_t)blockIdx.y * 128 + warpM + mt * 16 + g + hf * 8;
            float v[16];
#pragma unroll
            for (int nt = 0; nt < 8; nt++) {
                v[nt * 2]     = acc[mt][nt][hf * 2];
                v[nt * 2 + 1] = acc[mt][nt][hf * 2 + 1];
            }
            if (mode == 0) {
                int n = (int)(m & (N_TOK - 1));
                float sc = 1.0f / (float)g_sizes[batch[n]];
#pragma unroll
                for (int k = 0; k < 16; k++) v[k] *= sc;
            } else {
                float s = 0.f, s2 = 0.f;
#pragma unroll
                for (int k = 0; k < 16; k++) { s += v[k]; s2 += v[k] * v[k]; }
                s  += __shfl_xor_sync(0xffffffffu, s, 1);
                s  += __shfl_xor_sync(0xffffffffu, s, 2);
                s2 += __shfl_xor_sync(0xffffffffu, s2, 1);
                s2 += __shfl_xor_sync(0xffffffffu, s2, 2);
                float mu = s * (1.0f / 64.0f);
                float var = s2 * (1.0f / 64.0f) - mu * mu;
                float rs = rsqrtf(var + 1e-6f);
#pragma unroll
                for (int nt = 0; nt < 8; nt++) {
                    int cl = ((warpN + nt * 8 + c2 * 2) & 63); // head-local
                    v[nt * 2]     = (v[nt * 2]     - mu) * rs * lw[cl]     + lb[cl];
                    v[nt * 2 + 1] = (v[nt * 2 + 1] - mu) * rs * lw[cl + 1] + lb[cl + 1];
                }
            }
            size_t base = m * DIM + colbase + c2 * 2;
#pragma unroll
            for (int nt = 0; nt < 8; nt++) {
                ushort2 uh, ul;
                split2(v[nt * 2], v[nt * 2 + 1], uh, ul);
                *(ushort2*)((unsigned short*)dh + base + nt * 8) = uh;
                *(ushort2*)((unsigned short*)dl + base + nt * 8) = ul;
            }
        }
    }
#undef QST
#undef Q_ISSUE
}

// ---------------- GEMM2: out = attn_hi @ w_out^T + bias (1-term) ------------
#define OG_SMEM (2 * 2 * TEN_BYTES)   // 73728

__global__ __launch_bounds__(256, 2)
void out_gemm_kernel(const __half* __restrict__ Ah, const __half* __restrict__ Bh,
                     float* __restrict__ C, const float* __restrict__ bias) {
    extern __shared__ __align__(16) char smem[];
    uint32_t sb = smem_u32(smem);
    int tid = threadIdx.x, wid = tid >> 5, lane = tid & 31;
    int warpM = (wid & 3) * 32;
    int warpN = (wid >> 2) * 64;
    int g = lane >> 2, c2 = lane & 3;

    uint32_t aoff = (lane & 15) * 144 + (lane >> 4) * 16;
    uint32_t boff = ((lane & 7) + ((lane >> 4) << 3)) * 144 + ((lane >> 3) & 1) * 16;

    const __half* pAh = Ah + (size_t)blockIdx.y * 128 * KDIM;
    const __half* pBh = Bh + (size_t)blockIdx.x * 128 * KDIM;

#define OST(s, t) (sb + ((s) * 2 + (t)) * TEN_BYTES)
#define O_ISSUE(s, k0)                            \
    do {                                          \
        issue_slab(OST(s, 0), pAh, (k0), tid);    \
        issue_slab(OST(s, 1), pBh, (k0), tid);    \
        asm volatile("cp.async.commit_group;");   \
    } while (0)

    O_ISSUE(0, 0);
    O_ISSUE(1, 64);

    float acc[2][8][4];
#pragma unroll
    for (int i = 0; i < 2; i++)
#pragma unroll
        for (int j = 0; j < 8; j++)
#pragma unroll
            for (int k = 0; k < 4; k++) acc[i][j][k] = 0.0f;

    for (int it = 0; it < 8; it++) {
        int s = it % 3;
        // NOTE: 2 slabs/stage -> 3 stages fit in 6 slots? No: use 2-stage + 2 barriers.
        s = it & 1;
        if (it < 7) asm volatile("cp.async.wait_group 1;");
        else        asm volatile("cp.async.wait_group 0;");
        __syncthreads();
        uint32_t aA0 = OST(s, 0) + warpM * 144 + aoff;
        uint32_t aB0 = OST(s, 1) + warpN * 144 + boff;
#pragma unroll
        for (int kk = 0; kk < 4; kk++) {
            int ko = kk * 32;
            uint32_t ah[2][4], bf[4][4];
            LDMX4(ah[0], aA0 + ko); LDMX4(ah[1], aA0 + 16 * 144 + ko);
#pragma unroll
            for (int p = 0; p < 4; p++) LDMX4(bf[p], aB0 + p * 16 * 144 + ko);
#pragma unroll
            for (int mt = 0; mt < 2; mt++)
#pragma unroll
                for (int nt = 0; nt < 8; nt++)
                    mma16816(acc[mt][nt], ah[mt], &bf[nt >> 1][(nt & 1) * 2]);
        }
        __syncthreads();
        if (it + 2 < 8) O_ISSUE(s, (it + 2) * 64);
    }

#pragma unroll
    for (int mt = 0; mt < 2; mt++) {
        size_t m0 = (size_t)blockIdx.y * 128 + warpM + mt * 16 + g;
#pragma unroll
        for (int nt = 0; nt < 8; nt++) {
            int nc = blockIdx.x * 128 + warpN + nt * 8 + c2 * 2;
            float b0 = bias[nc], b1 = bias[nc + 1];
            *(float2*)(C + m0 * DIM + nc) =
                make_float2(acc[mt][nt][0] + b0, acc[mt][nt][1] + b1);
            *(float2*)(C + (m0 + 8) * DIM + nc) =
                make_float2(acc[mt][nt][2] + b0, acc[mt][nt][3] + b1);
        }
    }
#undef OST
#undef O_ISSUE
}

// ---------------- ktvT[b,h,g] (tensor, 3-term, ldmatrix.trans) --------------
#define KT_SLAB  (64 * 144)
#define KT_STAGE (4 * KT_SLAB)
#define KT_SMEM  (2 * KT_STAGE)      // 73728

__global__ __launch_bounds__(128, 2)
void ktvmma_kernel() {
    int gseg = blockIdx.x & 31;
    int h = (blockIdx.x >> 5) & 7;
    int b = blockIdx.x >> 8;
    int s0 = g_off[gseg], s1 = g_off[gseg + 1];
    int NCH = (s1 - s0 + 63) >> 6;
    if (NCH <= 0) NCH = 1;

    extern __shared__ __align__(16) char smem[];
    uint32_t sb = smem_u32(smem);
    int tid = threadIdx.x, wid = tid >> 5, lane = tid & 31;
    int lg = lane >> 2, c2 = lane & 3;

#define KT_ISSUE(st, c)                                                        \
    do {                                                                       \
        int t0 = s0 + (c) * 64;                                                \
        uint32_t base = sb + (st) * KT_STAGE;                                  \
        char* cbase = smem + (st) * KT_STAGE;                                  \
        _Pragma("unroll")                                                      \
        for (int i = 0; i < 4; i++) {                                          \
            int id = tid + i * 128;                                            \
            int row = id >> 3, ch = id & 7;                                    \
            int tok = t0 + row;                                                \
            uint32_t so = row * 144 + ch * 16;                                 \
            if (tok < s1) {                                                    \
                size_t go = ((size_t)b * N_TOK + tok) * DIM + h * DH + ch * 8; \
                CPA16(base + 0 * KT_SLAB + so, g_k_hi + go);                   \
                CPA16(base + 1 * KT_SLAB + so, g_k_lo + go);                   \
                CPA16(base + 2 * KT_SLAB + so, g_v_hi + go);                   \
                CPA16(base + 3 * KT_SLAB + so, g_v_lo + go);                   \
            } else {                                                           \
                uint4 z = make_uint4(0, 0, 0, 0);                              \
                *(uint4*)(cbase + 0 * KT_SLAB + so) = z;                       \
                *(uint4*)(cbase + 1 * KT_SLAB + so) = z;                       \
                *(uint4*)(cbase + 2 * KT_SLAB + so) = z;                       \
                *(uint4*)(cbase + 3 * KT_SLAB + so) = z;                       \
            }                                                                  \
        }                                                                      \
        asm volatile("cp.async.commit_group;");                                \
    } while (0)

    KT_ISSUE(0, 0);
    if (NCH > 1) KT_ISSUE(1, 1);

    uint32_t aoffT = ((lane & 7) + (lane >> 4) * 8) * 144 + ((lane >> 3) & 1) * 16;
    uint32_t boffT = ((lane & 7) + ((lane >> 3) & 1) * 8) * 144 + (lane >> 4) * 16;

    float acc[8][4];
#pragma unroll
    for (int j = 0; j < 8; j++)
#pragma unroll
        for (int k = 0; k < 4; k++) acc[j][k] = 0.0f;

    for (int c = 0; c < NCH; c++) {
        int st = c & 1;
        if (c + 2 <= NCH) asm volatile("cp.async.wait_group 1;");
        else              asm volatile("cp.async.wait_group 0;");
        __syncthreads();
        uint32_t base = sb + st * KT_STAGE;
        uint32_t aKh = base + 0 * KT_SLAB + boffT;
        uint32_t aKl = base + 1 * KT_SLAB + boffT;
        uint32_t aVh = base + 2 * KT_SLAB + wid * 32 + aoffT;
        uint32_t aVl = base + 3 * KT_SLAB + wid * 32 + aoffT;
#pragma unroll
        for (int kk = 0; kk < 4; kk++) {
            int ko = kk * (16 * 144);
            uint32_t vh[4], vl[4], kh[4][4], kl[4][4];
            LDMX4T(vh, aVh + ko);
            LDMX4T(vl, aVl + ko);
#pragma unroll
            for (int nb = 0; nb < 4; nb++) {
                LDMX4T(kh[nb], aKh + nb * 32 + ko);
                LDMX4T(kl[nb], aKl + nb * 32 + ko);
            }
#pragma unroll
            for (int nt = 0; nt < 8; nt++) {
                mma16816(acc[nt], vh, &kh[nt >> 1][(nt & 1) * 2]);
                mma16816(acc[nt], vl, &kh[nt >> 1][(nt & 1) * 2]);
                mma16816(acc[nt], vh, &kl[nt >> 1][(nt & 1) * 2]);
            }
        }
        __syncthreads();
        if (c + 2 < NCH) KT_ISSUE(st, c + 2);
    }

    size_t kb = (size_t)blockIdx.x * (DH * DH);
    int r0 = wid * 16 + lg;
#pragma unroll
    for (int nt = 0; nt < 8; nt++) {
        int cidx = nt * 8 + c2 * 2;
        ushort2 uh, ul;
        split2(acc[nt][0], acc[nt][1], uh, ul);
        *(ushort2*)((unsigned short*)g_ktvT_hi + kb + (size_t)r0 * DH + cidx) = uh;
        *(ushort2*)((unsigned short*)g_ktvT_lo + kb + (size_t)r0 * DH + cidx) = ul;
        split2(acc[nt][2], acc[nt][3], uh, ul);
        *(ushort2*)((unsigned short*)g_ktvT_hi + kb + (size_t)(r0 + 8) * DH + cidx) = uh;
        *(ushort2*)((unsigned short*)g_ktvT_lo + kb + (size_t)(r0 + 8) * DH + cidx) = ul;
    }
#undef KT_ISSUE
}

// ---------------- attn tile = q_tile @ ktvT (tensor, 3-term, hi-only out) ---
#define AP_QSLAB (128 * 144)
#define AP_TSLAB (64 * 144)
#define AP_SMEM  (2 * AP_QSLAB + 2 * AP_TSLAB)   // 55296

__global__ __launch_bounds__(256, 2)
void applymma_kernel() {
    int h = blockIdx.x, ti = blockIdx.y, b = blockIdx.z;
    int nval = g_tile_nval[ti];
    if (nval == 0) return;
    int gseg = g_tile_g[ti];
    int tok0 = g_tile_tok0[ti];

    extern __shared__ __align__(16) char smem[];
    uint32_t sb = smem_u32(smem);
    uint32_t sQh = sb, sQl = sb + AP_QSLAB;
    uint32_t sTh = sb + 2 * AP_QSLAB, sTl = sTh + AP_TSLAB;

    int tid = threadIdx.x, wid = tid >> 5, lane = tid & 31;
    int warpM = (wid & 3) * 32;
    int warpN = (wid >> 2) * 32;
    int g = lane >> 2, c2 = lane & 3;

    {
        size_t qrow0 = (size_t)b * N_TOK + tok0;
#pragma unroll
        for (int t = 0; t < 4; t++) {
            int id = tid + t * 256;          // 0..1023
            int row = id >> 3, ch = id & 7;
            size_t go = (qrow0 + row) * DIM + h * DH + ch * 8;
            CPA16(sQh + row * 144 + ch * 16, (const __half*)g_q_hi + go);
            CPA16(sQl + row * 144 + ch * 16, (const __half*)g_q_lo + go);
        }
        size_t kbase = ((size_t)((b * HEADS + h) * NGRAPH + gseg)) * DH * DH;
#pragma unroll
        for (int t = 0; t < 2; t++) {
            int id = tid + t * 256;          // 0..511
            int row = id >> 3, ch = id & 7;
            size_t ko = kbase + (size_t)row * DH + ch * 8;
            CPA16(sTh + row * 144 + ch * 16, (const __half*)g_ktvT_hi + ko);
            CPA16(sTl + row * 144 + ch * 16, (const __half*)g_ktvT_lo + ko);
        }
        asm volatile("cp.async.commit_group;");
        asm volatile("cp.async.wait_group 0;");
        __syncthreads();
    }

    uint32_t aoff = (lane & 15) * 144 + (lane >> 4) * 16;
    uint32_t boff = ((lane & 7) + ((lane >> 4) << 3)) * 144 + ((lane >> 3) & 1) * 16;

    float acc[2][4][4];
#pragma unroll
    for (int i = 0; i < 2; i++)
#pragma unroll
        for (int j = 0; j < 4; j++)
#pragma unroll
            for (int k = 0; k < 4; k++) acc[i][j][k] = 0.0f;

    uint32_t aQh = sQh + warpM * 144 + aoff;
    uint32_t aQl = sQl + warpM * 144 + aoff;
    uint32_t aTh = sTh + warpN * 144 + boff;
    uint32_t aTl = sTl + warpN * 144 + boff;

#pragma unroll
    for (int kk = 0; kk < 4; kk++) {
        int ko = kk * 32;
        uint32_t qh[2][4], ql[2][4], bh[2][4], bl[2][4];
        LDMX4(qh[0], aQh + ko); LDMX4(qh[1], aQh + 16 * 144 + ko);
        LDMX4(ql[0], aQl + ko); LDMX4(ql[1], aQl + 16 * 144 + ko);
        LDMX4(bh[0], aTh + ko); LDMX4(bh[1], aTh + 16 * 144 + ko);
        LDMX4(bl[0], aTl + ko); LDMX4(bl[1], aTl + 16 * 144 + ko);
#pragma unroll
        for (int mt = 0; mt < 2; mt++)
#pragma unroll
            for (int nt = 0; nt < 4; nt++) {
                const uint32_t* bph = &bh[nt >> 1][(nt & 1) * 2];
                const uint32_t* bpl = &bl[nt >> 1][(nt & 1) * 2];
                mma16816(acc[mt][nt], qh[mt], bph);
                mma16816(acc[mt][nt], ql[mt], bph);
                mma16816(acc[mt][nt], qh[mt], bpl);
            }
    }

    // masked epilogue -> attn hi only (GEMM2 is 1-term now)
#pragma unroll
    for (int mt = 0; mt < 2; mt++) {
#pragma unroll
        for (int hf = 0; hf < 2; hf++) {
            int r = warpM + mt * 16 + g + hf * 8;
            if (r < nval) {
                size_t base = ((size_t)b * N_TOK + tok0 + r) * DIM + h * DH + warpN + c2 * 2;
#pragma unroll
                for (int nt = 0; nt < 4; nt++) {
                    float f0 = acc[mt][nt][hf * 2], f1 = acc[mt][nt][hf * 2 + 1];
                    ushort2 uh = make_ushort2(
                        __half_as_ushort(__float2half_rn(f0)),
                        __half_as_ushort(__float2half_rn(f1)));
                    *(ushort2*)((unsigned short*)g_attn_hi + base + nt * 8) = uh;
                }
            }
        }
    }
}

// ---------------- launch ----------------------------------------------------
extern "C" void kernel_launch(void* const* d_in, const int* in_sizes, int n_in,
                              void* d_out, int out_size) {
    const float* x     = (const float*)d_in[0];
    const float* w_qkv = (const float*)d_in[1];
    const float* ln1w  = (const float*)d_in[2];
    const float* ln1b  = (const float*)d_in[3];
    const float* ln2w  = (const float*)d_in[4];
    const float* ln2b  = (const float*)d_in[5];
    const float* w_out = (const float*)d_in[6];
    const float* b_out = (const float*)d_in[7];
    const int*   batch = (const int*)d_in[8];
    float* out = (float*)d_out;

    __half *ah_p, *b1h_p, *b2h_p, *ath_p;
    cudaGetSymbolAddress((void**)&ah_p,  g_a_hi);
    cudaGetSymbolAddress((void**)&b1h_p, g_b1_hi);
    cudaGetSymbolAddress((void**)&b2h_p, g_b2_hi);
    cudaGetSymbolAddress((void**)&ath_p, g_attn_hi);

    cudaFuncSetAttribute(qkv_gemm_kernel, cudaFuncAttributeMaxDynamicSharedMemorySize, QK_SMEM);
    cudaFuncSetAttribute(out_gemm_kernel, cudaFuncAttributeMaxDynamicSharedMemorySize, OG_SMEM);
    cudaFuncSetAttribute(ktvmma_kernel,   cudaFuncAttributeMaxDynamicSharedMemorySize, KT_SMEM);
    cudaFuncSetAttribute(applymma_kernel, cudaFuncAttributeMaxDynamicSharedMemorySize, AP_SMEM);

    // 0) segment offsets + tile tables
    hist_kernel<<<1, 256>>>(batch);

    // 1) conversions
    conv_round_kernel<<<4096, 256>>>(x, ah_p, (long)M_ROWS * KDIM / 4);
    conv_w_kernel<<<1024, 256>>>(w_qkv, w_out);

    // 2) qkv GEMM (1-term fp16, 3-stage) + fused epilogue
    qkv_gemm_kernel<<<dim3(QKV3 / 128, M_ROWS / 128), 256, QK_SMEM>>>(
        ah_p, b1h_p, batch, ln1w, ln1b, ln2w, ln2b);

    // 3) ktvT per (b,h,g) (tensor, 3-term)
    ktvmma_kernel<<<B_SZ * HEADS * NGRAPH, 128, KT_SMEM>>>();

    // 4) attn = qn @ ktv (tensor, masked ragged tiles) -> attn hi only
    applymma_kernel<<<dim3(HEADS, TILEMAX, B_SZ), 256, AP_SMEM>>>();

    // 5) out = attn_hi @ w_outT + bias (1-term)
    out_gemm_kernel<<<dim3(DIM / 128, M_ROWS / 128), 256, OG_SMEM>>>(
        ath_p, b2h_p, out, b_out);
}